// round 12
// baseline (speedup 1.0000x reference)
#include <cuda_runtime.h>
#include <cuda_fp16.h>
#include <math.h>

// ---------------- problem constants ----------------
#define NN   100000
#define EE0  1600000            // raw edges
#define EETOT (EE0 + NN)        // + self loops
#define C1   64                 // in channels
#define H1   4                  // heads layer1
#define HC1  128                // H1*D1
#define OUTC 32                 // layer2 out channels
#define NB_SCAN 98              // ceil(NN/1024)
#define LOG2E 1.4426950408889634f

typedef unsigned long long u64;
#define FMA_X2(d, a, b, c) \
    asm("fma.rn.f32x2 %0, %1, %2, %3;" : "=l"(d) : "l"(a), "l"(b), "l"(c))
#define PACK2(d, lo, hi) \
    asm("mov.b64 %0, {%1, %2};" : "=l"(d) : "f"(lo), "f"(hi))
#define UNPACK2(lo, hi, s) \
    asm("mov.b64 {%0, %1}, %2;" : "=f"(lo), "=f"(hi) : "l"(s))

union F4U2 { float4 f4; u64 u[2]; };

// ---------------- scratch (device globals; no allocation) ----------------
__device__ __half g_h1h[NN * HC1];      // layer1 features (fp16, gather-only)
__device__ __half g_out1h[NN * HC1];    // elu(agg1 + b1) (fp16, gemm2 input)
__device__ float  g_al_src1[NN * H1];   // pre-scaled by log2(e)
__device__ float  g_al_dst1[NN * H1];

__device__ float  g_h2f[NN * OUTC];     // layer2 features (fp32, L2-resident)
__device__ float  g_al_src2[NN];        // pre-scaled by log2(e)
__device__ float  g_al_dst2[NN];

// CSR build
__device__ int g_deg[NN];
__device__ int g_cursor[NN];
__device__ int g_bsum[NB_SCAN];
__device__ int g_boff[NB_SCAN];
__device__ int g_off[NN + 1];
__device__ int g_esrc[EETOT];
// monotonic handoff counters [cnt,rel] x 4 — NEVER reset (BSS-zeroed at load);
// each handoff consumes NB_SCAN tickets per replay, waiters compare per-generation
__device__ int g_sync[8];

// ---------------- helpers ----------------
__device__ __forceinline__ float ex2(float x) {
    float r;
    asm("ex2.approx.ftz.f32 %0, %1;" : "=f"(r) : "f"(x));
    return r;
}
// weight from pre-scaled logit sum: 2^(leaky(x))
__device__ __forceinline__ float wfun(float x) {
    return ex2(fmaxf(x, 0.2f * x));
}

// int64 little-endian edges => int32 view has zero high words (indices < 2^31)
__device__ __forceinline__ int detect_is64(const int* __restrict__ ei) {
    int zeros = 0;
#pragma unroll
    for (int k = 0; k < 16; k++) zeros += (ei[2 * k + 1] == 0);
    return zeros == 16;
}

__device__ __forceinline__ void h4load(const __half* p, float& f0, float& f1,
                                       float& f2, float& f3) {
    uint2 u = *reinterpret_cast<const uint2*>(p);
    __half2 a = *reinterpret_cast<__half2*>(&u.x);
    __half2 b = *reinterpret_cast<__half2*>(&u.y);
    float2 fa = __half22float2(a), fb = __half22float2(b);
    f0 = fa.x; f1 = fa.y; f2 = fb.x; f3 = fb.y;
}

// monotonic grid-wide handoff among NB_SCAN resident blocks
__device__ __forceinline__ void mono_handoff(int idx) {
    __syncthreads();
    if (threadIdx.x == 0) {
        __threadfence();
        int tk = atomicAdd(&g_sync[2 * idx], 1);
        int g = tk / NB_SCAN;
        if ((tk % NB_SCAN) == NB_SCAN - 1) atomicAdd(&g_sync[2 * idx + 1], 1);
        while (atomicAdd(&g_sync[2 * idx + 1], 0) < g + 1) { }
        __threadfence();
    }
    __syncthreads();
}

// ---------------- GEMM1 + fused logits1 ----------------
#define G1_ROWS 64
__global__ __launch_bounds__(256) void gemm1_kernel(const float* __restrict__ x,
                                                    const float* __restrict__ W,
                                                    const float* __restrict__ asrc,
                                                    const float* __restrict__ adst) {
    __shared__ float xst[C1][G1_ROWS];   // [k][row] 16 KB
    __shared__ float Ws[C1][HC1];        // 32 KB
    int tid = threadIdx.x;
    int row0 = blockIdx.x * G1_ROWS;

    const float4* W4 = (const float4*)W;
    float4* Ws4 = (float4*)Ws;
#pragma unroll
    for (int i = 0; i < 8; i++) Ws4[tid + 256 * i] = W4[tid + 256 * i];
#pragma unroll
    for (int i = 0; i < 4; i++) {
        int idx = tid + 256 * i;          // float4 idx; 16 per row
        int r = idx >> 4, k4 = idx & 15;
        int row = row0 + r;
        float4 v = make_float4(0.f, 0.f, 0.f, 0.f);
        if (row < NN) v = *(const float4*)&x[row * C1 + k4 * 4];
        xst[k4 * 4 + 0][r] = v.x; xst[k4 * 4 + 1][r] = v.y;
        xst[k4 * 4 + 2][r] = v.z; xst[k4 * 4 + 3][r] = v.w;
    }
    __syncthreads();

    int lane = tid & 31, w = tid >> 5;
    int rb = w * 8;
    u64 acc2[4][4];                     // [row-pair][col]
#pragma unroll
    for (int m = 0; m < 4; m++)
#pragma unroll
        for (int c = 0; c < 4; c++) acc2[m][c] = 0ull;

#pragma unroll
    for (int k = 0; k < C1; k++) {
        F4U2 xa, xb;
        xa.f4 = *(float4*)&xst[k][rb];
        xb.f4 = *(float4*)&xst[k][rb + 4];
        float4 wv = *(float4*)&Ws[k][lane * 4];
        u64 wd[4];
        PACK2(wd[0], wv.x, wv.x); PACK2(wd[1], wv.y, wv.y);
        PACK2(wd[2], wv.z, wv.z); PACK2(wd[3], wv.w, wv.w);
        u64 xp[4] = {xa.u[0], xa.u[1], xb.u[0], xb.u[1]};
#pragma unroll
        for (int m = 0; m < 4; m++) {
            FMA_X2(acc2[m][0], xp[m], wd[0], acc2[m][0]);
            FMA_X2(acc2[m][1], xp[m], wd[1], acc2[m][1]);
            FMA_X2(acc2[m][2], xp[m], wd[2], acc2[m][2]);
            FMA_X2(acc2[m][3], xp[m], wd[3], acc2[m][3]);
        }
    }

    float acc[8][4];
#pragma unroll
    for (int m = 0; m < 4; m++)
#pragma unroll
        for (int c = 0; c < 4; c++)
            UNPACK2(acc[2 * m][c], acc[2 * m + 1][c], acc2[m][c]);

    float4 av = *(const float4*)&asrc[lane * 4];
    float4 bv = *(const float4*)&adst[lane * 4];
    int head = lane >> 3;
#pragma unroll
    for (int r = 0; r < 8; r++) {
        int row = row0 + rb + r;
        if (row < NN) {
            __half2 p0 = __floats2half2_rn(acc[r][0], acc[r][1]);
            __half2 p1 = __floats2half2_rn(acc[r][2], acc[r][3]);
            uint2 u;
            u.x = *reinterpret_cast<unsigned*>(&p0);
            u.y = *reinterpret_cast<unsigned*>(&p1);
            *reinterpret_cast<uint2*>(&g_h1h[row * HC1 + lane * 4]) = u;
        }
        float ps = acc[r][0] * av.x + acc[r][1] * av.y + acc[r][2] * av.z + acc[r][3] * av.w;
        float pd = acc[r][0] * bv.x + acc[r][1] * bv.y + acc[r][2] * bv.z + acc[r][3] * bv.w;
#pragma unroll
        for (int off = 4; off >= 1; off >>= 1) {
            ps += __shfl_down_sync(0xffffffffu, ps, off);
            pd += __shfl_down_sync(0xffffffffu, pd, off);
        }
        if ((lane & 7) == 0 && row < NN) {
            g_al_src1[row * H1 + head] = ps * LOG2E;
            g_al_dst1[row * H1 + head] = pd * LOG2E;
        }
    }
}

// ---------------- zero + hist + scan + scatter: one persistent kernel -------
__global__ __launch_bounds__(1024) void histscan_kernel(const int* __restrict__ ei) {
    __shared__ int warp_tot[32];
    __shared__ int block_base;
    __shared__ int sh_is64;
    int t = threadIdx.x;
    int i = blockIdx.x * 1024 + t;
    int lane = t & 31, w = t >> 5;
    if (t == 0) sh_is64 = detect_is64(ei);

    // ---- phase -1: zero deg (self-init) ----
    for (int n = blockIdx.x * 1024 + t; n < NN; n += NB_SCAN * 1024)
        g_deg[n] = 0;
    __syncthreads();
    int is64 = sh_is64;
    mono_handoff(0);                    // all zeros visible

    // ---- phase 0: dst histogram (grid-stride) ----
    for (int e = blockIdx.x * 1024 + t; e < EETOT; e += NB_SCAN * 1024) {
        int d;
        if (e >= EE0) d = e - EE0;
        else d = is64 ? ei[2 * (EE0 + e)] : ei[EE0 + e];
        atomicAdd(&g_deg[d], 1);
    }
    mono_handoff(1);                    // all histogram atomics visible

    // ---- phase 1: scan ----
    int deg = (i < NN) ? g_deg[i] : 0;
    int sum = deg;
#pragma unroll
    for (int o = 1; o < 32; o <<= 1) {
        int u = __shfl_up_sync(0xffffffffu, sum, o);
        if (lane >= o) sum += u;
    }
    if (lane == 31) warp_tot[w] = sum;
    __syncthreads();
    if (w == 0) {
        int s = warp_tot[lane];
#pragma unroll
        for (int o = 1; o < 32; o <<= 1) {
            int u = __shfl_up_sync(0xffffffffu, s, o);
            if (lane >= o) s += u;
        }
        warp_tot[lane] = s;
    }
    __syncthreads();
    int wbase = (w > 0) ? warp_tot[w - 1] : 0;
    int inc = wbase + sum;              // inclusive scan within block
    if (t == 1023) g_bsum[blockIdx.x] = inc;
    __syncthreads();                    // bsum written before ticket

    // handoff (custom): last-arriving block's warp 0 scans the block sums
    if (w == 0) {
        int tk = 0;
        if (lane == 0) {
            __threadfence();
            tk = atomicAdd(&g_sync[4], 1);
        }
        tk = __shfl_sync(0xffffffffu, tk, 0);
        int gen = tk / NB_SCAN;
        if ((tk % NB_SCAN) == NB_SCAN - 1) {
            int carry = 0;
#pragma unroll
            for (int c = 0; c < 4; c++) {
                int idx = c * 32 + lane;
                int v = (idx < NB_SCAN) ? g_bsum[idx] : 0;
                int s = v;
#pragma unroll
                for (int o = 1; o < 32; o <<= 1) {
                    int u = __shfl_up_sync(0xffffffffu, s, o);
                    if (lane >= o) s += u;
                }
                if (idx < NB_SCAN) g_boff[idx] = carry + s - v;   // exclusive
                carry += __shfl_sync(0xffffffffu, s, 31);
            }
            __threadfence();
            if (lane == 0) atomicAdd(&g_sync[5], 1);
        }
        if (lane == 0) {
            while (atomicAdd(&g_sync[5], 0) < gen + 1) { }
            __threadfence();
            block_base = g_boff[blockIdx.x];
        }
    }
    __syncthreads();
    int base = block_base;
    if (i == 0) g_off[0] = 0;
    if (i < NN) {
        int end = base + inc;
        g_off[i + 1] = end;
        g_cursor[i] = end - deg;        // start offset; scatter bumps this
    }
    mono_handoff(3);                    // all cursors visible before scatter

    // ---- phase 2: scatter (grid-stride) ----
    for (int e = blockIdx.x * 1024 + t; e < EETOT; e += NB_SCAN * 1024) {
        int s, d;
        if (e >= EE0) { s = d = e - EE0; }
        else if (is64) { s = ei[2 * e]; d = ei[2 * (EE0 + e)]; }
        else           { s = ei[e];     d = ei[EE0 + e]; }
        int pos = atomicAdd(&g_cursor[d], 1);
        g_esrc[pos] = s;
    }
}

// ---------------- fused agg1: warp per dst node, CSR, int4 edge loads --------
#define AGG1_EDGE(S)                                                         \
    do {                                                                     \
        float xx = als[(S) * H1 + h] + adh;                                  \
        float a0, a1, a2, a3;                                                \
        h4load(&h1p[(S) * HC1 + lane4], a0, a1, a2, a3);                     \
        float ww = wfun(xx);                                                 \
        den += ww;                                                           \
        acc.x += ww * a0; acc.y += ww * a1;                                  \
        acc.z += ww * a2; acc.w += ww * a3;                                  \
    } while (0)

__global__ void agg1_kernel(const float* __restrict__ b1) {
    int gid = blockIdx.x * blockDim.x + threadIdx.x;
    int d = gid >> 5;
    int lane = gid & 31;
    if (d >= NN) return;
    int h = lane >> 3;
    int lane4 = lane * 4;
    const float* __restrict__ als = g_al_src1;
    const int* __restrict__ esrc = g_esrc;
    const __half* __restrict__ h1p = g_h1h;
    float adh = g_al_dst1[d * H1 + h];
    int j0 = g_off[d], j1 = g_off[d + 1];
    float4 acc = make_float4(0.f, 0.f, 0.f, 0.f);
    float den = 0.f;
    int j = j0;
    // peel to 16B alignment of esrc
    while (j < j1 && (j & 3)) { AGG1_EDGE(esrc[j]); j++; }
    for (; j + 3 < j1; j += 4) {
        int4 s4 = *reinterpret_cast<const int4*>(&esrc[j]);
        float x0 = als[s4.x * H1 + h] + adh;
        float x1 = als[s4.y * H1 + h] + adh;
        float x2 = als[s4.z * H1 + h] + adh;
        float x3 = als[s4.w * H1 + h] + adh;
        float a0, a1, a2, a3, c0, c1, c2, c3;
        float e0, e1, e2, e3, f0, f1, f2, f3;
        h4load(&h1p[s4.x * HC1 + lane4], a0, a1, a2, a3);
        h4load(&h1p[s4.y * HC1 + lane4], c0, c1, c2, c3);
        h4load(&h1p[s4.z * HC1 + lane4], e0, e1, e2, e3);
        h4load(&h1p[s4.w * HC1 + lane4], f0, f1, f2, f3);
        float w0 = wfun(x0), w1 = wfun(x1), w2 = wfun(x2), w3 = wfun(x3);
        den += (w0 + w1) + (w2 + w3);
        acc.x += w0 * a0 + w1 * c0 + w2 * e0 + w3 * f0;
        acc.y += w0 * a1 + w1 * c1 + w2 * e1 + w3 * f1;
        acc.z += w0 * a2 + w1 * c2 + w2 * e2 + w3 * f2;
        acc.w += w0 * a3 + w1 * c3 + w2 * e3 + w3 * f3;
    }
    for (; j < j1; j++) AGG1_EDGE(esrc[j]);

    float inv = 1.f / den;      // self-loop guarantees den > 0
    float4 b = *reinterpret_cast<const float4*>(&b1[lane4]);
    float4 o;
    o.x = acc.x * inv + b.x; o.y = acc.y * inv + b.y;
    o.z = acc.z * inv + b.z; o.w = acc.w * inv + b.w;
    o.x = o.x > 0.f ? o.x : expm1f(o.x);
    o.y = o.y > 0.f ? o.y : expm1f(o.y);
    o.z = o.z > 0.f ? o.z : expm1f(o.z);
    o.w = o.w > 0.f ? o.w : expm1f(o.w);
    __half2 p0 = __floats2half2_rn(o.x, o.y);
    __half2 p1 = __floats2half2_rn(o.z, o.w);
    uint2 u;
    u.x = *reinterpret_cast<unsigned*>(&p0);
    u.y = *reinterpret_cast<unsigned*>(&p1);
    *reinterpret_cast<uint2*>(&g_out1h[d * HC1 + lane4]) = u;
}

// ---------------- GEMM2 + fused logits2 (register-tiled, K-chunked) ----------
#define G2_ROWS 128
#define G2_PAD  132
__global__ __launch_bounds__(256) void gemm2_kernel(const float* __restrict__ W2,
                                                    const float* __restrict__ asrc,
                                                    const float* __restrict__ adst) {
    __shared__ float xst[64][G2_PAD];    // ~33 KB  [k][row]
    __shared__ float Wc[64][OUTC];       // 8 KB    [k][col] (current K-chunk)
    int tid = threadIdx.x;
    int row0 = blockIdx.x * G2_ROWS;
    int lane = tid & 31, w = tid >> 5;
    int row_sub = lane >> 3;             // 0..3
    int cg = lane & 7;                   // 0..7
    int rbase = w * 16 + row_sub * 4;    // 4 consecutive rows per thread

    u64 acc2[2][4];                      // [row-pair][col]
#pragma unroll
    for (int m = 0; m < 2; m++)
#pragma unroll
        for (int c = 0; c < 4; c++) acc2[m][c] = 0ull;

#pragma unroll
    for (int kc = 0; kc < 2; kc++) {
        {
            const float4* Wg = (const float4*)(W2 + kc * 64 * OUTC);
            float4* Wc4 = (float4*)Wc;
            Wc4[tid] = Wg[tid];
            Wc4[tid + 256] = Wg[tid + 256];
        }
#pragma unroll
        for (int i = 0; i < 4; i++) {
            int idx = tid + 256 * i;     // 0..1023
            int k8 = idx >> 7;           // 0..7
            int row = idx & 127;
            int grow = row0 + row;
            uint4 v = make_uint4(0u, 0u, 0u, 0u);
            if (grow < NN) v = *(const uint4*)&g_out1h[grow * HC1 + kc * 64 + k8 * 8];
            const unsigned uu[4] = {v.x, v.y, v.z, v.w};
#pragma unroll
            for (int q = 0; q < 4; q++) {
                __half2 hh = *reinterpret_cast<const __half2*>(&uu[q]);
                float2 ff = __half22float2(hh);
                xst[k8 * 8 + q * 2 + 0][row] = ff.x;
                xst[k8 * 8 + q * 2 + 1][row] = ff.y;
            }
        }
        __syncthreads();

#pragma unroll 16
        for (int k = 0; k < 64; k++) {
            F4U2 xa;
            xa.f4 = *(float4*)&xst[k][rbase];          // 4 rows
            float4 wv = *(float4*)&Wc[k][cg * 4];      // 4 cols
            u64 wd0, wd1, wd2, wd3;
            PACK2(wd0, wv.x, wv.x); PACK2(wd1, wv.y, wv.y);
            PACK2(wd2, wv.z, wv.z); PACK2(wd3, wv.w, wv.w);
#pragma unroll
            for (int m = 0; m < 2; m++) {
                FMA_X2(acc2[m][0], xa.u[m], wd0, acc2[m][0]);
                FMA_X2(acc2[m][1], xa.u[m], wd1, acc2[m][1]);
                FMA_X2(acc2[m][2], xa.u[m], wd2, acc2[m][2]);
                FMA_X2(acc2[m][3], xa.u[m], wd3, acc2[m][3]);
            }
        }
        __syncthreads();
    }

    float acc[4][4];                     // [row][col]
#pragma unroll
    for (int m = 0; m < 2; m++)
#pragma unroll
        for (int c = 0; c < 4; c++)
            UNPACK2(acc[2 * m][c], acc[2 * m + 1][c], acc2[m][c]);

    float4 av = *(const float4*)&asrc[cg * 4];
    float4 bv = *(const float4*)&adst[cg * 4];
#pragma unroll
    for (int r = 0; r < 4; r++) {
        int row = row0 + rbase + r;
        if (row < NN)
            *(float4*)&g_h2f[row * OUTC + cg * 4] = *(float4*)acc[r];
        float ps = acc[r][0] * av.x + acc[r][1] * av.y + acc[r][2] * av.z + acc[r][3] * av.w;
        float pd = acc[r][0] * bv.x + acc[r][1] * bv.y + acc[r][2] * bv.z + acc[r][3] * bv.w;
#pragma unroll
        for (int off = 4; off >= 1; off >>= 1) {
            ps += __shfl_down_sync(0xffffffffu, ps, off);
            pd += __shfl_down_sync(0xffffffffu, pd, off);
        }
        if (cg == 0 && row < NN) {
            g_al_src2[row] = ps * LOG2E;
            g_al_dst2[row] = pd * LOG2E;
        }
    }
}

// ---------------- fused agg2: warp per dst node, int4 edge loads -------------
#define AGG2_EDGE(S)                                                         \
    do {                                                                     \
        float ww = wfun(als[(S)] + ad2);                                     \
        den += ww;                                                           \
        acc += ww * h2p[(S) * OUTC + lane];                                  \
    } while (0)

__global__ void agg2_kernel(float* __restrict__ dout, const float* __restrict__ b2) {
    int gid = blockIdx.x * blockDim.x + threadIdx.x;
    int d = gid >> 5;
    int lane = gid & 31;
    if (d >= NN) return;
    const float* __restrict__ als = g_al_src2;
    const int* __restrict__ esrc = g_esrc;
    const float* __restrict__ h2p = g_h2f;
    float ad2 = g_al_dst2[d];
    int j0 = g_off[d], j1 = g_off[d + 1];
    float acc = 0.f, den = 0.f;
    int j = j0;
    while (j < j1 && (j & 3)) { AGG2_EDGE(esrc[j]); j++; }
    for (; j + 3 < j1; j += 4) {
        int4 s4 = *reinterpret_cast<const int4*>(&esrc[j]);
        float x0 = als[s4.x] + ad2, x1 = als[s4.y] + ad2;
        float x2 = als[s4.z] + ad2, x3 = als[s4.w] + ad2;
        float v0 = h2p[s4.x * OUTC + lane];
        float v1 = h2p[s4.y * OUTC + lane];
        float v2 = h2p[s4.z * OUTC + lane];
        float v3 = h2p[s4.w * OUTC + lane];
        float w0 = wfun(x0), w1 = wfun(x1), w2 = wfun(x2), w3 = wfun(x3);
        den += (w0 + w1) + (w2 + w3);
        acc += w0 * v0 + w1 * v1 + w2 * v2 + w3 * v3;
    }
    for (; j < j1; j++) AGG2_EDGE(esrc[j]);
    dout[d * OUTC + lane] = acc / den + b2[lane];
}

// ---------------- launch ----------------
extern "C" void kernel_launch(void* const* d_in, const int* in_sizes, int n_in,
                              void* d_out, int out_size) {
    const float* x        = (const float*)d_in[0];
    const int*   ei       = (const int*)d_in[1];
    const float* W1       = (const float*)d_in[2];
    const float* att_src1 = (const float*)d_in[3];
    const float* att_dst1 = (const float*)d_in[4];
    const float* b1       = (const float*)d_in[5];
    const float* W2       = (const float*)d_in[6];
    const float* att_src2 = (const float*)d_in[7];
    const float* att_dst2 = (const float*)d_in[8];
    const float* b2       = (const float*)d_in[9];
    float* dout = (float*)d_out;

    const int T = 256;
    // host-side objects only (no device allocation); leaked intentionally —
    // kernel_launch runs O(1) times
    cudaStream_t s2;
    cudaStreamCreate(&s2);
    cudaEvent_t eFork, eH;
    cudaEventCreateWithFlags(&eFork, cudaEventDisableTiming);
    cudaEventCreateWithFlags(&eH,    cudaEventDisableTiming);

    // fork: CSR build (self-initializing) runs concurrently with gemm1
    cudaEventRecord(eFork, 0);
    cudaStreamWaitEvent(s2, eFork, 0);
    histscan_kernel<<<NB_SCAN, 1024, 0, s2>>>(ei);
    cudaEventRecord(eH, s2);

    gemm1_kernel<<<(NN + G1_ROWS - 1) / G1_ROWS, 256>>>(x, W1, att_src1, att_dst1);

    cudaStreamWaitEvent(0, eH, 0);
    agg1_kernel<<<(NN * 32 + T - 1) / T, T>>>(b1);
    gemm2_kernel<<<(NN + G2_ROWS - 1) / G2_ROWS, 256>>>(W2, att_src2, att_dst2);
    agg2_kernel<<<(NN * 32 + T - 1) / T, T>>>(dout, b2);
}

// round 13
// speedup vs baseline: 1.0227x; 1.0227x over previous
#include <cuda_runtime.h>
#include <cuda_fp16.h>
#include <math.h>

// ---------------- problem constants ----------------
#define NN   100000
#define EE0  1600000            // raw edges
#define EETOT (EE0 + NN)        // + self loops
#define C1   64                 // in channels
#define H1   4                  // heads layer1
#define HC1  128                // H1*D1
#define OUTC 32                 // layer2 out channels
#define NB_SCAN 98              // ceil(NN/1024)
#define LOG2E 1.4426950408889634f

typedef unsigned long long u64;
#define FMA_X2(d, a, b, c) \
    asm("fma.rn.f32x2 %0, %1, %2, %3;" : "=l"(d) : "l"(a), "l"(b), "l"(c))
#define PACK2(d, lo, hi) \
    asm("mov.b64 %0, {%1, %2};" : "=l"(d) : "f"(lo), "f"(hi))
#define UNPACK2(lo, hi, s) \
    asm("mov.b64 {%0, %1}, %2;" : "=f"(lo), "=f"(hi) : "l"(s))

union F4U2 { float4 f4; u64 u[2]; };

// ---------------- scratch (device globals; no allocation) ----------------
__device__ __half g_h1h[NN * HC1];      // layer1 features (fp16, gather-only)
__device__ __half g_out1h[NN * HC1];    // elu(agg1 + b1) (fp16, gemm2 input)
__device__ float  g_al_src1[NN * H1];   // pre-scaled by log2(e)
__device__ float  g_al_dst1[NN * H1];

__device__ float  g_h2f[NN * OUTC];     // layer2 features (fp32, L2-resident)
__device__ float  g_al_src2[NN];        // pre-scaled by log2(e)
__device__ float  g_al_dst2[NN];

// CSR build
__device__ int g_deg[NN];
__device__ int g_cursor[NN];
__device__ int g_bsum[NB_SCAN];
__device__ int g_boff[NB_SCAN];
__device__ int g_off[NN + 1];
__device__ int g_esrc[EETOT];
// monotonic handoff counters [cnt,rel] x 4 — NEVER reset (BSS-zeroed at load)
__device__ int g_sync[8];

// ---------------- helpers ----------------
__device__ __forceinline__ float ex2(float x) {
    float r;
    asm("ex2.approx.ftz.f32 %0, %1;" : "=f"(r) : "f"(x));
    return r;
}
// weight from pre-scaled logit sum: 2^(leaky(x))
__device__ __forceinline__ float wfun(float x) {
    return ex2(fmaxf(x, 0.2f * x));
}

// int64 little-endian edges => int32 view has zero high words (indices < 2^31)
__device__ __forceinline__ int detect_is64(const int* __restrict__ ei) {
    int zeros = 0;
#pragma unroll
    for (int k = 0; k < 16; k++) zeros += (ei[2 * k + 1] == 0);
    return zeros == 16;
}

__device__ __forceinline__ void h4load(const __half* p, float& f0, float& f1,
                                       float& f2, float& f3) {
    uint2 u = *reinterpret_cast<const uint2*>(p);
    __half2 a = *reinterpret_cast<__half2*>(&u.x);
    __half2 b = *reinterpret_cast<__half2*>(&u.y);
    float2 fa = __half22float2(a), fb = __half22float2(b);
    f0 = fa.x; f1 = fa.y; f2 = fb.x; f3 = fb.y;
}

// monotonic grid-wide handoff among NB_SCAN resident blocks
__device__ __forceinline__ void mono_handoff(int idx) {
    __syncthreads();
    if (threadIdx.x == 0) {
        __threadfence();
        int tk = atomicAdd(&g_sync[2 * idx], 1);
        int g = tk / NB_SCAN;
        if ((tk % NB_SCAN) == NB_SCAN - 1) atomicAdd(&g_sync[2 * idx + 1], 1);
        while (atomicAdd(&g_sync[2 * idx + 1], 0) < g + 1) { }
        __threadfence();
    }
    __syncthreads();
}

// ---------------- GEMM1 + fused logits1 ----------------
#define G1_ROWS 64
__global__ __launch_bounds__(256) void gemm1_kernel(const float* __restrict__ x,
                                                    const float* __restrict__ W,
                                                    const float* __restrict__ asrc,
                                                    const float* __restrict__ adst) {
    __shared__ float xst[C1][G1_ROWS];   // [k][row] 16 KB
    __shared__ float Ws[C1][HC1];        // 32 KB
    int tid = threadIdx.x;
    int row0 = blockIdx.x * G1_ROWS;

    const float4* W4 = (const float4*)W;
    float4* Ws4 = (float4*)Ws;
#pragma unroll
    for (int i = 0; i < 8; i++) Ws4[tid + 256 * i] = W4[tid + 256 * i];
#pragma unroll
    for (int i = 0; i < 4; i++) {
        int idx = tid + 256 * i;          // float4 idx; 16 per row
        int r = idx >> 4, k4 = idx & 15;
        int row = row0 + r;
        float4 v = make_float4(0.f, 0.f, 0.f, 0.f);
        if (row < NN) v = *(const float4*)&x[row * C1 + k4 * 4];
        xst[k4 * 4 + 0][r] = v.x; xst[k4 * 4 + 1][r] = v.y;
        xst[k4 * 4 + 2][r] = v.z; xst[k4 * 4 + 3][r] = v.w;
    }
    __syncthreads();

    int lane = tid & 31, w = tid >> 5;
    int rb = w * 8;
    u64 acc2[4][4];                     // [row-pair][col]
#pragma unroll
    for (int m = 0; m < 4; m++)
#pragma unroll
        for (int c = 0; c < 4; c++) acc2[m][c] = 0ull;

#pragma unroll
    for (int k = 0; k < C1; k++) {
        F4U2 xa, xb;
        xa.f4 = *(float4*)&xst[k][rb];
        xb.f4 = *(float4*)&xst[k][rb + 4];
        float4 wv = *(float4*)&Ws[k][lane * 4];
        u64 wd[4];
        PACK2(wd[0], wv.x, wv.x); PACK2(wd[1], wv.y, wv.y);
        PACK2(wd[2], wv.z, wv.z); PACK2(wd[3], wv.w, wv.w);
        u64 xp[4] = {xa.u[0], xa.u[1], xb.u[0], xb.u[1]};
#pragma unroll
        for (int m = 0; m < 4; m++) {
            FMA_X2(acc2[m][0], xp[m], wd[0], acc2[m][0]);
            FMA_X2(acc2[m][1], xp[m], wd[1], acc2[m][1]);
            FMA_X2(acc2[m][2], xp[m], wd[2], acc2[m][2]);
            FMA_X2(acc2[m][3], xp[m], wd[3], acc2[m][3]);
        }
    }

    float acc[8][4];
#pragma unroll
    for (int m = 0; m < 4; m++)
#pragma unroll
        for (int c = 0; c < 4; c++)
            UNPACK2(acc[2 * m][c], acc[2 * m + 1][c], acc2[m][c]);

    float4 av = *(const float4*)&asrc[lane * 4];
    float4 bv = *(const float4*)&adst[lane * 4];
    int head = lane >> 3;
#pragma unroll
    for (int r = 0; r < 8; r++) {
        int row = row0 + rb + r;
        if (row < NN) {
            __half2 p0 = __floats2half2_rn(acc[r][0], acc[r][1]);
            __half2 p1 = __floats2half2_rn(acc[r][2], acc[r][3]);
            uint2 u;
            u.x = *reinterpret_cast<unsigned*>(&p0);
            u.y = *reinterpret_cast<unsigned*>(&p1);
            *reinterpret_cast<uint2*>(&g_h1h[row * HC1 + lane * 4]) = u;
        }
        float ps = acc[r][0] * av.x + acc[r][1] * av.y + acc[r][2] * av.z + acc[r][3] * av.w;
        float pd = acc[r][0] * bv.x + acc[r][1] * bv.y + acc[r][2] * bv.z + acc[r][3] * bv.w;
#pragma unroll
        for (int off = 4; off >= 1; off >>= 1) {
            ps += __shfl_down_sync(0xffffffffu, ps, off);
            pd += __shfl_down_sync(0xffffffffu, pd, off);
        }
        if ((lane & 7) == 0 && row < NN) {
            g_al_src1[row * H1 + head] = ps * LOG2E;
            g_al_dst1[row * H1 + head] = pd * LOG2E;
        }
    }
}

// ---------------- zero + hist + scan + scatter: one persistent kernel -------
__global__ __launch_bounds__(1024) void histscan_kernel(const int* __restrict__ ei) {
    __shared__ int warp_tot[32];
    __shared__ int block_base;
    __shared__ int sh_is64;
    int t = threadIdx.x;
    int i = blockIdx.x * 1024 + t;
    int lane = t & 31, w = t >> 5;
    if (t == 0) sh_is64 = detect_is64(ei);

    // ---- phase -1: zero deg (self-init) ----
    for (int n = blockIdx.x * 1024 + t; n < NN; n += NB_SCAN * 1024)
        g_deg[n] = 0;
    __syncthreads();
    int is64 = sh_is64;
    mono_handoff(0);                    // all zeros visible

    // ---- phase 0: dst histogram (grid-stride) ----
    for (int e = blockIdx.x * 1024 + t; e < EETOT; e += NB_SCAN * 1024) {
        int d;
        if (e >= EE0) d = e - EE0;
        else d = is64 ? ei[2 * (EE0 + e)] : ei[EE0 + e];
        atomicAdd(&g_deg[d], 1);
    }
    mono_handoff(1);                    // all histogram atomics visible

    // ---- phase 1: scan ----
    int deg = (i < NN) ? g_deg[i] : 0;
    int sum = deg;
#pragma unroll
    for (int o = 1; o < 32; o <<= 1) {
        int u = __shfl_up_sync(0xffffffffu, sum, o);
        if (lane >= o) sum += u;
    }
    if (lane == 31) warp_tot[w] = sum;
    __syncthreads();
    if (w == 0) {
        int s = warp_tot[lane];
#pragma unroll
        for (int o = 1; o < 32; o <<= 1) {
            int u = __shfl_up_sync(0xffffffffu, s, o);
            if (lane >= o) s += u;
        }
        warp_tot[lane] = s;
    }
    __syncthreads();
    int wbase = (w > 0) ? warp_tot[w - 1] : 0;
    int inc = wbase + sum;              // inclusive scan within block
    if (t == 1023) g_bsum[blockIdx.x] = inc;
    __syncthreads();                    // bsum written before ticket

    // handoff (custom): last-arriving block's warp 0 scans the block sums
    if (w == 0) {
        int tk = 0;
        if (lane == 0) {
            __threadfence();
            tk = atomicAdd(&g_sync[4], 1);
        }
        tk = __shfl_sync(0xffffffffu, tk, 0);
        int gen = tk / NB_SCAN;
        if ((tk % NB_SCAN) == NB_SCAN - 1) {
            int carry = 0;
#pragma unroll
            for (int c = 0; c < 4; c++) {
                int idx = c * 32 + lane;
                int v = (idx < NB_SCAN) ? g_bsum[idx] : 0;
                int s = v;
#pragma unroll
                for (int o = 1; o < 32; o <<= 1) {
                    int u = __shfl_up_sync(0xffffffffu, s, o);
                    if (lane >= o) s += u;
                }
                if (idx < NB_SCAN) g_boff[idx] = carry + s - v;   // exclusive
                carry += __shfl_sync(0xffffffffu, s, 31);
            }
            __threadfence();
            if (lane == 0) atomicAdd(&g_sync[5], 1);
        }
        if (lane == 0) {
            while (atomicAdd(&g_sync[5], 0) < gen + 1) { }
            __threadfence();
            block_base = g_boff[blockIdx.x];
        }
    }
    __syncthreads();
    int base = block_base;
    if (i == 0) g_off[0] = 0;
    if (i < NN) {
        int end = base + inc;
        g_off[i + 1] = end;
        g_cursor[i] = end - deg;        // start offset; scatter bumps this
    }
    mono_handoff(3);                    // all cursors visible before scatter

    // ---- phase 2: scatter (grid-stride) ----
    for (int e = blockIdx.x * 1024 + t; e < EETOT; e += NB_SCAN * 1024) {
        int s, d;
        if (e >= EE0) { s = d = e - EE0; }
        else if (is64) { s = ei[2 * e]; d = ei[2 * (EE0 + e)]; }
        else           { s = ei[e];     d = ei[EE0 + e]; }
        int pos = atomicAdd(&g_cursor[d], 1);
        g_esrc[pos] = s;
    }
}

// ---------------- fused agg1: warp per dst node, CSR, no atomics ----------------
__global__ void agg1_kernel(const float* __restrict__ b1) {
    int gid = blockIdx.x * blockDim.x + threadIdx.x;
    int d = gid >> 5;
    int lane = gid & 31;
    if (d >= NN) return;
    int h = lane >> 3;
    const float* __restrict__ als = g_al_src1;
    const int* __restrict__ esrc = g_esrc;
    const __half* __restrict__ h1p = g_h1h;
    float adh = g_al_dst1[d * H1 + h];
    int j0 = g_off[d], j1 = g_off[d + 1];
    float4 acc = make_float4(0.f, 0.f, 0.f, 0.f);
    float den = 0.f;
    int j = j0;
    for (; j + 3 < j1; j += 4) {
        int s0 = esrc[j],     s1 = esrc[j + 1];
        int s2 = esrc[j + 2], s3 = esrc[j + 3];
        float x0 = als[s0 * H1 + h] + adh;
        float x1 = als[s1 * H1 + h] + adh;
        float x2 = als[s2 * H1 + h] + adh;
        float x3 = als[s3 * H1 + h] + adh;
        float a0, a1, a2, a3, c0, c1, c2, c3;
        float e0, e1, e2, e3, f0, f1, f2, f3;
        h4load(&h1p[s0 * HC1 + lane * 4], a0, a1, a2, a3);
        h4load(&h1p[s1 * HC1 + lane * 4], c0, c1, c2, c3);
        h4load(&h1p[s2 * HC1 + lane * 4], e0, e1, e2, e3);
        h4load(&h1p[s3 * HC1 + lane * 4], f0, f1, f2, f3);
        float w0 = wfun(x0), w1 = wfun(x1), w2 = wfun(x2), w3 = wfun(x3);
        den += (w0 + w1) + (w2 + w3);
        acc.x += w0 * a0 + w1 * c0 + w2 * e0 + w3 * f0;
        acc.y += w0 * a1 + w1 * c1 + w2 * e1 + w3 * f1;
        acc.z += w0 * a2 + w1 * c2 + w2 * e2 + w3 * f2;
        acc.w += w0 * a3 + w1 * c3 + w2 * e3 + w3 * f3;
    }
    for (; j < j1; j++) {
        int s0 = esrc[j];
        float x0 = als[s0 * H1 + h] + adh;
        float a0, a1, a2, a3;
        h4load(&h1p[s0 * HC1 + lane * 4], a0, a1, a2, a3);
        float w0 = wfun(x0);
        den += w0;
        acc.x += w0 * a0; acc.y += w0 * a1;
        acc.z += w0 * a2; acc.w += w0 * a3;
    }
    float inv = 1.f / den;      // self-loop guarantees den > 0
    float4 b = *reinterpret_cast<const float4*>(&b1[lane * 4]);
    float4 o;
    o.x = acc.x * inv + b.x; o.y = acc.y * inv + b.y;
    o.z = acc.z * inv + b.z; o.w = acc.w * inv + b.w;
    o.x = o.x > 0.f ? o.x : expm1f(o.x);
    o.y = o.y > 0.f ? o.y : expm1f(o.y);
    o.z = o.z > 0.f ? o.z : expm1f(o.z);
    o.w = o.w > 0.f ? o.w : expm1f(o.w);
    __half2 p0 = __floats2half2_rn(o.x, o.y);
    __half2 p1 = __floats2half2_rn(o.z, o.w);
    uint2 u;
    u.x = *reinterpret_cast<unsigned*>(&p0);
    u.y = *reinterpret_cast<unsigned*>(&p1);
    *reinterpret_cast<uint2*>(&g_out1h[d * HC1 + lane * 4]) = u;
}

// ---------------- GEMM2 + fused logits2 (8 rows x 4 cols per thread) --------
// h2[N,32] = out1[N,128] @ W2[128,32]; 256 rows per block, 32-k chunks
#define G2_ROWS 256
#define G2_PAD  260
__global__ __launch_bounds__(256) void gemm2_kernel(const float* __restrict__ W2,
                                                    const float* __restrict__ asrc,
                                                    const float* __restrict__ adst) {
    __shared__ float xst[32][G2_PAD];    // ~33.3 KB  [k][row]
    __shared__ float Wc[32][OUTC];       // 4 KB      [k][col] (current K-chunk)
    int tid = threadIdx.x;
    int row0 = blockIdx.x * G2_ROWS;
    int lane = tid & 31, w = tid >> 5;
    int row_sub = lane >> 3;             // 0..3
    int cg = lane & 7;                   // 0..7
    int rbase = w * 32 + row_sub * 8;    // 8 consecutive rows per thread

    u64 acc2[4][4];                      // [row-pair][col]
#pragma unroll
    for (int m = 0; m < 4; m++)
#pragma unroll
        for (int c = 0; c < 4; c++) acc2[m][c] = 0ull;

#pragma unroll
    for (int kc = 0; kc < 4; kc++) {
        // load W chunk (32x32 floats = 256 float4, one per thread)
        {
            const float4* Wg = (const float4*)(W2 + kc * 32 * OUTC);
            ((float4*)Wc)[tid] = Wg[tid];
        }
        // load x chunk transposed: k8-major mapping (conflict-free STS)
#pragma unroll
        for (int i = 0; i < 4; i++) {
            int idx = tid + 256 * i;     // 0..1023
            int k8 = idx >> 8;           // 0..3
            int row = idx & 255;
            int grow = row0 + row;
            uint4 v = make_uint4(0u, 0u, 0u, 0u);
            if (grow < NN) v = *(const uint4*)&g_out1h[grow * HC1 + kc * 32 + k8 * 8];
            const unsigned uu[4] = {v.x, v.y, v.z, v.w};
#pragma unroll
            for (int q = 0; q < 4; q++) {
                __half2 hh = *reinterpret_cast<const __half2*>(&uu[q]);
                float2 ff = __half22float2(hh);
                xst[k8 * 8 + q * 2 + 0][row] = ff.x;
                xst[k8 * 8 + q * 2 + 1][row] = ff.y;
            }
        }
        __syncthreads();

#pragma unroll 8
        for (int k = 0; k < 32; k++) {
            F4U2 xa, xb;
            xa.f4 = *(float4*)&xst[k][rbase];          // rows 0..3
            xb.f4 = *(float4*)&xst[k][rbase + 4];      // rows 4..7
            float4 wv = *(float4*)&Wc[k][cg * 4];      // 4 cols
            u64 wd0, wd1, wd2, wd3;
            PACK2(wd0, wv.x, wv.x); PACK2(wd1, wv.y, wv.y);
            PACK2(wd2, wv.z, wv.z); PACK2(wd3, wv.w, wv.w);
            u64 xp[4] = {xa.u[0], xa.u[1], xb.u[0], xb.u[1]};
#pragma unroll
            for (int m = 0; m < 4; m++) {
                FMA_X2(acc2[m][0], xp[m], wd0, acc2[m][0]);
                FMA_X2(acc2[m][1], xp[m], wd1, acc2[m][1]);
                FMA_X2(acc2[m][2], xp[m], wd2, acc2[m][2]);
                FMA_X2(acc2[m][3], xp[m], wd3, acc2[m][3]);
            }
        }
        __syncthreads();
    }

    float acc[8][4];                     // [row][col]
#pragma unroll
    for (int m = 0; m < 4; m++)
#pragma unroll
        for (int c = 0; c < 4; c++)
            UNPACK2(acc[2 * m][c], acc[2 * m + 1][c], acc2[m][c]);

    float4 av = *(const float4*)&asrc[cg * 4];
    float4 bv = *(const float4*)&adst[cg * 4];
#pragma unroll
    for (int r = 0; r < 8; r++) {
        int row = row0 + rbase + r;
        if (row < NN)
            *(float4*)&g_h2f[row * OUTC + cg * 4] = *(float4*)acc[r];
        float ps = acc[r][0] * av.x + acc[r][1] * av.y + acc[r][2] * av.z + acc[r][3] * av.w;
        float pd = acc[r][0] * bv.x + acc[r][1] * bv.y + acc[r][2] * bv.z + acc[r][3] * bv.w;
#pragma unroll
        for (int off = 4; off >= 1; off >>= 1) {
            ps += __shfl_down_sync(0xffffffffu, ps, off);
            pd += __shfl_down_sync(0xffffffffu, pd, off);
        }
        if (cg == 0 && row < NN) {
            g_al_src2[row] = ps * LOG2E;
            g_al_dst2[row] = pd * LOG2E;
        }
    }
}

// ---------------- fused agg2: warp per dst node ----------------
__global__ void agg2_kernel(float* __restrict__ dout, const float* __restrict__ b2) {
    int gid = blockIdx.x * blockDim.x + threadIdx.x;
    int d = gid >> 5;
    int lane = gid & 31;
    if (d >= NN) return;
    const float* __restrict__ als = g_al_src2;
    const int* __restrict__ esrc = g_esrc;
    const float* __restrict__ h2p = g_h2f;
    float ad2 = g_al_dst2[d];
    int j0 = g_off[d], j1 = g_off[d + 1];
    float acc = 0.f, den = 0.f;
    int j = j0;
    for (; j + 3 < j1; j += 4) {
        int s0 = esrc[j],     s1 = esrc[j + 1];
        int s2 = esrc[j + 2], s3 = esrc[j + 3];
        float x0 = als[s0] + ad2, x1 = als[s1] + ad2;
        float x2 = als[s2] + ad2, x3 = als[s3] + ad2;
        float v0 = h2p[s0 * OUTC + lane];
        float v1 = h2p[s1 * OUTC + lane];
        float v2 = h2p[s2 * OUTC + lane];
        float v3 = h2p[s3 * OUTC + lane];
        float w0 = wfun(x0), w1 = wfun(x1), w2 = wfun(x2), w3 = wfun(x3);
        den += (w0 + w1) + (w2 + w3);
        acc += w0 * v0 + w1 * v1 + w2 * v2 + w3 * v3;
    }
    for (; j < j1; j++) {
        int s0 = esrc[j];
        float w0 = wfun(als[s0] + ad2);
        den += w0;
        acc += w0 * h2p[s0 * OUTC + lane];
    }
    dout[d * OUTC + lane] = acc / den + b2[lane];
}

// ---------------- launch ----------------
extern "C" void kernel_launch(void* const* d_in, const int* in_sizes, int n_in,
                              void* d_out, int out_size) {
    const float* x        = (const float*)d_in[0];
    const int*   ei       = (const int*)d_in[1];
    const float* W1       = (const float*)d_in[2];
    const float* att_src1 = (const float*)d_in[3];
    const float* att_dst1 = (const float*)d_in[4];
    const float* b1       = (const float*)d_in[5];
    const float* W2       = (const float*)d_in[6];
    const float* att_src2 = (const float*)d_in[7];
    const float* att_dst2 = (const float*)d_in[8];
    const float* b2       = (const float*)d_in[9];
    float* dout = (float*)d_out;

    const int T = 256;
    // host-side objects only (no device allocation); leaked intentionally —
    // kernel_launch runs O(1) times
    cudaStream_t s2;
    cudaStreamCreate(&s2);
    cudaEvent_t eFork, eH;
    cudaEventCreateWithFlags(&eFork, cudaEventDisableTiming);
    cudaEventCreateWithFlags(&eH,    cudaEventDisableTiming);

    // fork: CSR build (self-initializing) runs concurrently with gemm1
    cudaEventRecord(eFork, 0);
    cudaStreamWaitEvent(s2, eFork, 0);
    histscan_kernel<<<NB_SCAN, 1024, 0, s2>>>(ei);
    cudaEventRecord(eH, s2);

    gemm1_kernel<<<(NN + G1_ROWS - 1) / G1_ROWS, 256>>>(x, W1, att_src1, att_dst1);

    cudaStreamWaitEvent(0, eH, 0);
    agg1_kernel<<<(NN * 32 + T - 1) / T, T>>>(b1);
    gemm2_kernel<<<(NN + G2_ROWS - 1) / G2_ROWS, 256>>>(W2, att_src2, att_dst2);
    agg2_kernel<<<(NN * 32 + T - 1) / T, T>>>(dout, b2);
}

// round 14
// speedup vs baseline: 1.1058x; 1.0813x over previous
#include <cuda_runtime.h>
#include <cuda_fp16.h>
#include <math.h>

// ---------------- problem constants ----------------
#define NN   100000
#define EE0  1600000            // raw edges
#define EETOT (EE0 + NN)        // + self loops
#define C1   64                 // in channels
#define H1   4                  // heads layer1
#define HC1  128                // H1*D1
#define OUTC 32                 // layer2 out channels
#define NB_SCAN 98              // ceil(NN/1024)
#define LOG2E 1.4426950408889634f

typedef unsigned long long u64;
#define FMA_X2(d, a, b, c) \
    asm("fma.rn.f32x2 %0, %1, %2, %3;" : "=l"(d) : "l"(a), "l"(b), "l"(c))
#define PACK2(d, lo, hi) \
    asm("mov.b64 %0, {%1, %2};" : "=l"(d) : "f"(lo), "f"(hi))
#define UNPACK2(lo, hi, s) \
    asm("mov.b64 {%0, %1}, %2;" : "=f"(lo), "=f"(hi) : "l"(s))

union F4U2 { float4 f4; u64 u[2]; };

// ---------------- scratch (device globals; no allocation) ----------------
__device__ __half g_h1h[NN * HC1];      // layer1 features (fp16, gather-only)
__device__ __half g_out1h[NN * HC1];    // elu(agg1 + b1) (fp16, gemm2 input)
__device__ float  g_al_src1[NN * H1];   // pre-scaled by log2(e)
__device__ float  g_al_dst1[NN * H1];

__device__ float  g_h2f[NN * OUTC];     // layer2 features (fp32, L2-resident)
__device__ float  g_al_src2[NN];        // pre-scaled by log2(e)
__device__ float  g_al_dst2[NN];

// CSR build
__device__ int g_deg[NN];
__device__ int g_cursor[NN];
__device__ int g_bsum[NB_SCAN];
__device__ int g_boff[NB_SCAN];
__device__ int g_off[NN + 1];
__device__ int g_esrc[EETOT];
// monotonic handoff counters [cnt,rel] x 4 — NEVER reset (BSS-zeroed at load)
__device__ int g_sync[8];

// ---------------- helpers ----------------
__device__ __forceinline__ float ex2(float x) {
    float r;
    asm("ex2.approx.ftz.f32 %0, %1;" : "=f"(r) : "f"(x));
    return r;
}
// weight from pre-scaled logit sum: 2^(leaky(x))
__device__ __forceinline__ float wfun(float x) {
    return ex2(fmaxf(x, 0.2f * x));
}

// int64 little-endian edges => int32 view has zero high words (indices < 2^31)
__device__ __forceinline__ int detect_is64(const int* __restrict__ ei) {
    int zeros = 0;
#pragma unroll
    for (int k = 0; k < 16; k++) zeros += (ei[2 * k + 1] == 0);
    return zeros == 16;
}

// monotonic grid-wide handoff among NB_SCAN resident blocks
__device__ __forceinline__ void mono_handoff(int idx) {
    __syncthreads();
    if (threadIdx.x == 0) {
        __threadfence();
        int tk = atomicAdd(&g_sync[2 * idx], 1);
        int g = tk / NB_SCAN;
        if ((tk % NB_SCAN) == NB_SCAN - 1) atomicAdd(&g_sync[2 * idx + 1], 1);
        while (atomicAdd(&g_sync[2 * idx + 1], 0) < g + 1) { }
        __threadfence();
    }
    __syncthreads();
}

// ---------------- GEMM1 + fused logits1 ----------------
#define G1_ROWS 64
__global__ __launch_bounds__(256) void gemm1_kernel(const float* __restrict__ x,
                                                    const float* __restrict__ W,
                                                    const float* __restrict__ asrc,
                                                    const float* __restrict__ adst) {
    __shared__ float xst[C1][G1_ROWS];   // [k][row] 16 KB
    __shared__ float Ws[C1][HC1];        // 32 KB
    int tid = threadIdx.x;
    int row0 = blockIdx.x * G1_ROWS;

    const float4* W4 = (const float4*)W;
    float4* Ws4 = (float4*)Ws;
#pragma unroll
    for (int i = 0; i < 8; i++) Ws4[tid + 256 * i] = W4[tid + 256 * i];
#pragma unroll
    for (int i = 0; i < 4; i++) {
        int idx = tid + 256 * i;          // float4 idx; 16 per row
        int r = idx >> 4, k4 = idx & 15;
        int row = row0 + r;
        float4 v = make_float4(0.f, 0.f, 0.f, 0.f);
        if (row < NN) v = *(const float4*)&x[row * C1 + k4 * 4];
        xst[k4 * 4 + 0][r] = v.x; xst[k4 * 4 + 1][r] = v.y;
        xst[k4 * 4 + 2][r] = v.z; xst[k4 * 4 + 3][r] = v.w;
    }
    __syncthreads();

    int lane = tid & 31, w = tid >> 5;
    int rb = w * 8;
    u64 acc2[4][4];                     // [row-pair][col]
#pragma unroll
    for (int m = 0; m < 4; m++)
#pragma unroll
        for (int c = 0; c < 4; c++) acc2[m][c] = 0ull;

#pragma unroll
    for (int k = 0; k < C1; k++) {
        F4U2 xa, xb;
        xa.f4 = *(float4*)&xst[k][rb];
        xb.f4 = *(float4*)&xst[k][rb + 4];
        float4 wv = *(float4*)&Ws[k][lane * 4];
        u64 wd[4];
        PACK2(wd[0], wv.x, wv.x); PACK2(wd[1], wv.y, wv.y);
        PACK2(wd[2], wv.z, wv.z); PACK2(wd[3], wv.w, wv.w);
        u64 xp[4] = {xa.u[0], xa.u[1], xb.u[0], xb.u[1]};
#pragma unroll
        for (int m = 0; m < 4; m++) {
            FMA_X2(acc2[m][0], xp[m], wd[0], acc2[m][0]);
            FMA_X2(acc2[m][1], xp[m], wd[1], acc2[m][1]);
            FMA_X2(acc2[m][2], xp[m], wd[2], acc2[m][2]);
            FMA_X2(acc2[m][3], xp[m], wd[3], acc2[m][3]);
        }
    }

    float acc[8][4];
#pragma unroll
    for (int m = 0; m < 4; m++)
#pragma unroll
        for (int c = 0; c < 4; c++)
            UNPACK2(acc[2 * m][c], acc[2 * m + 1][c], acc2[m][c]);

    float4 av = *(const float4*)&asrc[lane * 4];
    float4 bv = *(const float4*)&adst[lane * 4];
    int head = lane >> 3;
#pragma unroll
    for (int r = 0; r < 8; r++) {
        int row = row0 + rb + r;
        if (row < NN) {
            __half2 p0 = __floats2half2_rn(acc[r][0], acc[r][1]);
            __half2 p1 = __floats2half2_rn(acc[r][2], acc[r][3]);
            uint2 u;
            u.x = *reinterpret_cast<unsigned*>(&p0);
            u.y = *reinterpret_cast<unsigned*>(&p1);
            *reinterpret_cast<uint2*>(&g_h1h[row * HC1 + lane * 4]) = u;
        }
        float ps = acc[r][0] * av.x + acc[r][1] * av.y + acc[r][2] * av.z + acc[r][3] * av.w;
        float pd = acc[r][0] * bv.x + acc[r][1] * bv.y + acc[r][2] * bv.z + acc[r][3] * bv.w;
#pragma unroll
        for (int off = 4; off >= 1; off >>= 1) {
            ps += __shfl_down_sync(0xffffffffu, ps, off);
            pd += __shfl_down_sync(0xffffffffu, pd, off);
        }
        if ((lane & 7) == 0 && row < NN) {
            g_al_src1[row * H1 + head] = ps * LOG2E;
            g_al_dst1[row * H1 + head] = pd * LOG2E;
        }
    }
}

// ---------------- zero + hist + scan + scatter: one persistent kernel -------
__global__ __launch_bounds__(1024) void histscan_kernel(const int* __restrict__ ei) {
    __shared__ int warp_tot[32];
    __shared__ int block_base;
    __shared__ int sh_is64;
    int t = threadIdx.x;
    int i = blockIdx.x * 1024 + t;
    int lane = t & 31, w = t >> 5;
    if (t == 0) sh_is64 = detect_is64(ei);

    // ---- phase -1: zero deg (self-init) ----
    for (int n = blockIdx.x * 1024 + t; n < NN; n += NB_SCAN * 1024)
        g_deg[n] = 0;
    __syncthreads();
    int is64 = sh_is64;
    mono_handoff(0);                    // all zeros visible

    // ---- phase 0: dst histogram (grid-stride) ----
    for (int e = blockIdx.x * 1024 + t; e < EETOT; e += NB_SCAN * 1024) {
        int d;
        if (e >= EE0) d = e - EE0;
        else d = is64 ? ei[2 * (EE0 + e)] : ei[EE0 + e];
        atomicAdd(&g_deg[d], 1);
    }
    mono_handoff(1);                    // all histogram atomics visible

    // ---- phase 1: scan ----
    int deg = (i < NN) ? g_deg[i] : 0;
    int sum = deg;
#pragma unroll
    for (int o = 1; o < 32; o <<= 1) {
        int u = __shfl_up_sync(0xffffffffu, sum, o);
        if (lane >= o) sum += u;
    }
    if (lane == 31) warp_tot[w] = sum;
    __syncthreads();
    if (w == 0) {
        int s = warp_tot[lane];
#pragma unroll
        for (int o = 1; o < 32; o <<= 1) {
            int u = __shfl_up_sync(0xffffffffu, s, o);
            if (lane >= o) s += u;
        }
        warp_tot[lane] = s;
    }
    __syncthreads();
    int wbase = (w > 0) ? warp_tot[w - 1] : 0;
    int inc = wbase + sum;              // inclusive scan within block
    if (t == 1023) g_bsum[blockIdx.x] = inc;
    __syncthreads();                    // bsum written before ticket

    // handoff (custom): last-arriving block's warp 0 scans the block sums
    if (w == 0) {
        int tk = 0;
        if (lane == 0) {
            __threadfence();
            tk = atomicAdd(&g_sync[4], 1);
        }
        tk = __shfl_sync(0xffffffffu, tk, 0);
        int gen = tk / NB_SCAN;
        if ((tk % NB_SCAN) == NB_SCAN - 1) {
            int carry = 0;
#pragma unroll
            for (int c = 0; c < 4; c++) {
                int idx = c * 32 + lane;
                int v = (idx < NB_SCAN) ? g_bsum[idx] : 0;
                int s = v;
#pragma unroll
                for (int o = 1; o < 32; o <<= 1) {
                    int u = __shfl_up_sync(0xffffffffu, s, o);
                    if (lane >= o) s += u;
                }
                if (idx < NB_SCAN) g_boff[idx] = carry + s - v;   // exclusive
                carry += __shfl_sync(0xffffffffu, s, 31);
            }
            __threadfence();
            if (lane == 0) atomicAdd(&g_sync[5], 1);
        }
        if (lane == 0) {
            while (atomicAdd(&g_sync[5], 0) < gen + 1) { }
            __threadfence();
            block_base = g_boff[blockIdx.x];
        }
    }
    __syncthreads();
    int base = block_base;
    if (i == 0) g_off[0] = 0;
    if (i < NN) {
        int end = base + inc;
        g_off[i + 1] = end;
        g_cursor[i] = end - deg;        // start offset; scatter bumps this
    }
    mono_handoff(3);                    // all cursors visible before scatter

    // ---- phase 2: scatter (grid-stride) ----
    for (int e = blockIdx.x * 1024 + t; e < EETOT; e += NB_SCAN * 1024) {
        int s, d;
        if (e >= EE0) { s = d = e - EE0; }
        else if (is64) { s = ei[2 * e]; d = ei[2 * (EE0 + e)]; }
        else           { s = ei[e];     d = ei[EE0 + e]; }
        int pos = atomicAdd(&g_cursor[d], 1);
        g_esrc[pos] = s;
    }
}

// ---------------- fused agg1: HALF-warp per dst node (2 nodes/warp) ---------
// lane = half*16 + sl; sl covers channels [sl*8, sl*8+8) as uint4 of half2s
__global__ void agg1_kernel(const float* __restrict__ b1) {
    int gid = blockIdx.x * blockDim.x + threadIdx.x;
    int wid = gid >> 5;
    int lane = gid & 31;
    int half = lane >> 4;
    int sl = lane & 15;
    int d = wid * 2 + half;
    if (d >= NN) return;
    int h = sl >> 2;                     // head = channel/32
    int ch0 = sl * 8;
    const float* __restrict__ als = g_al_src1;
    const int* __restrict__ esrc = g_esrc;
    const __half* __restrict__ h1p = g_h1h;
    float adh = g_al_dst1[d * H1 + h];
    int j0 = g_off[d], j1 = g_off[d + 1];
    float acc[8];
#pragma unroll
    for (int q = 0; q < 8; q++) acc[q] = 0.f;
    float den = 0.f;
    int j = j0;
    for (; j + 1 < j1; j += 2) {
        int s0 = esrc[j], s1 = esrc[j + 1];
        float x0 = als[s0 * H1 + h] + adh;
        float x1 = als[s1 * H1 + h] + adh;
        uint4 v0 = *reinterpret_cast<const uint4*>(&h1p[s0 * HC1 + ch0]);
        uint4 v1 = *reinterpret_cast<const uint4*>(&h1p[s1 * HC1 + ch0]);
        float w0 = wfun(x0), w1 = wfun(x1);
        den += w0 + w1;
        const unsigned u0[4] = {v0.x, v0.y, v0.z, v0.w};
        const unsigned u1[4] = {v1.x, v1.y, v1.z, v1.w};
#pragma unroll
        for (int q = 0; q < 4; q++) {
            float2 f0 = __half22float2(*reinterpret_cast<const __half2*>(&u0[q]));
            float2 f1 = __half22float2(*reinterpret_cast<const __half2*>(&u1[q]));
            acc[2 * q + 0] += w0 * f0.x + w1 * f1.x;
            acc[2 * q + 1] += w0 * f0.y + w1 * f1.y;
        }
    }
    if (j < j1) {
        int s0 = esrc[j];
        float x0 = als[s0 * H1 + h] + adh;
        uint4 v0 = *reinterpret_cast<const uint4*>(&h1p[s0 * HC1 + ch0]);
        float w0 = wfun(x0);
        den += w0;
        const unsigned u0[4] = {v0.x, v0.y, v0.z, v0.w};
#pragma unroll
        for (int q = 0; q < 4; q++) {
            float2 f0 = __half22float2(*reinterpret_cast<const __half2*>(&u0[q]));
            acc[2 * q + 0] += w0 * f0.x;
            acc[2 * q + 1] += w0 * f0.y;
        }
    }
    float inv = 1.f / den;               // self-loop guarantees den > 0
    float4 ba = *reinterpret_cast<const float4*>(&b1[ch0]);
    float4 bb = *reinterpret_cast<const float4*>(&b1[ch0 + 4]);
    float ob[8];
    ob[0] = acc[0] * inv + ba.x; ob[1] = acc[1] * inv + ba.y;
    ob[2] = acc[2] * inv + ba.z; ob[3] = acc[3] * inv + ba.w;
    ob[4] = acc[4] * inv + bb.x; ob[5] = acc[5] * inv + bb.y;
    ob[6] = acc[6] * inv + bb.z; ob[7] = acc[7] * inv + bb.w;
#pragma unroll
    for (int q = 0; q < 8; q++) ob[q] = ob[q] > 0.f ? ob[q] : expm1f(ob[q]);
    uint4 o;
    __half2 p0 = __floats2half2_rn(ob[0], ob[1]);
    __half2 p1 = __floats2half2_rn(ob[2], ob[3]);
    __half2 p2 = __floats2half2_rn(ob[4], ob[5]);
    __half2 p3 = __floats2half2_rn(ob[6], ob[7]);
    o.x = *reinterpret_cast<unsigned*>(&p0);
    o.y = *reinterpret_cast<unsigned*>(&p1);
    o.z = *reinterpret_cast<unsigned*>(&p2);
    o.w = *reinterpret_cast<unsigned*>(&p3);
    *reinterpret_cast<uint4*>(&g_out1h[d * HC1 + ch0]) = o;
}

// ---------------- GEMM2 + fused logits2 (8 rows x 4 cols per thread) --------
#define G2_ROWS 256
#define G2_PAD  260
__global__ __launch_bounds__(256) void gemm2_kernel(const float* __restrict__ W2,
                                                    const float* __restrict__ asrc,
                                                    const float* __restrict__ adst) {
    __shared__ float xst[32][G2_PAD];    // ~33.3 KB  [k][row]
    __shared__ float Wc[32][OUTC];       // 4 KB      [k][col] (current K-chunk)
    int tid = threadIdx.x;
    int row0 = blockIdx.x * G2_ROWS;
    int lane = tid & 31, w = tid >> 5;
    int row_sub = lane >> 3;             // 0..3
    int cg = lane & 7;                   // 0..7
    int rbase = w * 32 + row_sub * 8;    // 8 consecutive rows per thread

    u64 acc2[4][4];                      // [row-pair][col]
#pragma unroll
    for (int m = 0; m < 4; m++)
#pragma unroll
        for (int c = 0; c < 4; c++) acc2[m][c] = 0ull;

#pragma unroll
    for (int kc = 0; kc < 4; kc++) {
        {
            const float4* Wg = (const float4*)(W2 + kc * 32 * OUTC);
            ((float4*)Wc)[tid] = Wg[tid];
        }
#pragma unroll
        for (int i = 0; i < 4; i++) {
            int idx = tid + 256 * i;     // 0..1023
            int k8 = idx >> 8;           // 0..3
            int row = idx & 255;
            int grow = row0 + row;
            uint4 v = make_uint4(0u, 0u, 0u, 0u);
            if (grow < NN) v = *(const uint4*)&g_out1h[grow * HC1 + kc * 32 + k8 * 8];
            const unsigned uu[4] = {v.x, v.y, v.z, v.w};
#pragma unroll
            for (int q = 0; q < 4; q++) {
                __half2 hh = *reinterpret_cast<const __half2*>(&uu[q]);
                float2 ff = __half22float2(hh);
                xst[k8 * 8 + q * 2 + 0][row] = ff.x;
                xst[k8 * 8 + q * 2 + 1][row] = ff.y;
            }
        }
        __syncthreads();

#pragma unroll 8
        for (int k = 0; k < 32; k++) {
            F4U2 xa, xb;
            xa.f4 = *(float4*)&xst[k][rbase];          // rows 0..3
            xb.f4 = *(float4*)&xst[k][rbase + 4];      // rows 4..7
            float4 wv = *(float4*)&Wc[k][cg * 4];      // 4 cols
            u64 wd0, wd1, wd2, wd3;
            PACK2(wd0, wv.x, wv.x); PACK2(wd1, wv.y, wv.y);
            PACK2(wd2, wv.z, wv.z); PACK2(wd3, wv.w, wv.w);
            u64 xp[4] = {xa.u[0], xa.u[1], xb.u[0], xb.u[1]};
#pragma unroll
            for (int m = 0; m < 4; m++) {
                FMA_X2(acc2[m][0], xp[m], wd0, acc2[m][0]);
                FMA_X2(acc2[m][1], xp[m], wd1, acc2[m][1]);
                FMA_X2(acc2[m][2], xp[m], wd2, acc2[m][2]);
                FMA_X2(acc2[m][3], xp[m], wd3, acc2[m][3]);
            }
        }
        __syncthreads();
    }

    float acc[8][4];                     // [row][col]
#pragma unroll
    for (int m = 0; m < 4; m++)
#pragma unroll
        for (int c = 0; c < 4; c++)
            UNPACK2(acc[2 * m][c], acc[2 * m + 1][c], acc2[m][c]);

    float4 av = *(const float4*)&asrc[cg * 4];
    float4 bv = *(const float4*)&adst[cg * 4];
#pragma unroll
    for (int r = 0; r < 8; r++) {
        int row = row0 + rbase + r;
        if (row < NN)
            *(float4*)&g_h2f[row * OUTC + cg * 4] = *(float4*)acc[r];
        float ps = acc[r][0] * av.x + acc[r][1] * av.y + acc[r][2] * av.z + acc[r][3] * av.w;
        float pd = acc[r][0] * bv.x + acc[r][1] * bv.y + acc[r][2] * bv.z + acc[r][3] * bv.w;
#pragma unroll
        for (int off = 4; off >= 1; off >>= 1) {
            ps += __shfl_down_sync(0xffffffffu, ps, off);
            pd += __shfl_down_sync(0xffffffffu, pd, off);
        }
        if (cg == 0 && row < NN) {
            g_al_src2[row] = ps * LOG2E;
            g_al_dst2[row] = pd * LOG2E;
        }
    }
}

// ---------------- fused agg2: HALF-warp per dst node (2 nodes/warp) ---------
// sl covers channels [sl*2, sl*2+2) as float2
__global__ void agg2_kernel(float* __restrict__ dout, const float* __restrict__ b2) {
    int gid = blockIdx.x * blockDim.x + threadIdx.x;
    int wid = gid >> 5;
    int lane = gid & 31;
    int half = lane >> 4;
    int sl = lane & 15;
    int d = wid * 2 + half;
    if (d >= NN) return;
    const float* __restrict__ als = g_al_src2;
    const int* __restrict__ esrc = g_esrc;
    const float* __restrict__ h2p = g_h2f;
    float ad2 = g_al_dst2[d];
    int j0 = g_off[d], j1 = g_off[d + 1];
    float acc0 = 0.f, acc1 = 0.f, den = 0.f;
    int j = j0;
    for (; j + 1 < j1; j += 2) {
        int s0 = esrc[j], s1 = esrc[j + 1];
        float x0 = als[s0] + ad2;
        float x1 = als[s1] + ad2;
        float2 v0 = *reinterpret_cast<const float2*>(&h2p[s0 * OUTC + sl * 2]);
        float2 v1 = *reinterpret_cast<const float2*>(&h2p[s1 * OUTC + sl * 2]);
        float w0 = wfun(x0), w1 = wfun(x1);
        den += w0 + w1;
        acc0 += w0 * v0.x + w1 * v1.x;
        acc1 += w0 * v0.y + w1 * v1.y;
    }
    if (j < j1) {
        int s0 = esrc[j];
        float w0 = wfun(als[s0] + ad2);
        float2 v0 = *reinterpret_cast<const float2*>(&h2p[s0 * OUTC + sl * 2]);
        den += w0;
        acc0 += w0 * v0.x;
        acc1 += w0 * v0.y;
    }
    float inv = 1.f / den;
    float2 bb = *reinterpret_cast<const float2*>(&b2[sl * 2]);
    float2 o;
    o.x = acc0 * inv + bb.x;
    o.y = acc1 * inv + bb.y;
    *reinterpret_cast<float2*>(&dout[d * OUTC + sl * 2]) = o;
}

// ---------------- launch ----------------
extern "C" void kernel_launch(void* const* d_in, const int* in_sizes, int n_in,
                              void* d_out, int out_size) {
    const float* x        = (const float*)d_in[0];
    const int*   ei       = (const int*)d_in[1];
    const float* W1       = (const float*)d_in[2];
    const float* att_src1 = (const float*)d_in[3];
    const float* att_dst1 = (const float*)d_in[4];
    const float* b1       = (const float*)d_in[5];
    const float* W2       = (const float*)d_in[6];
    const float* att_src2 = (const float*)d_in[7];
    const float* att_dst2 = (const float*)d_in[8];
    const float* b2       = (const float*)d_in[9];
    float* dout = (float*)d_out;

    const int T = 256;
    const long NWARPS = (NN + 1) / 2;           // 2 nodes per warp
    const int AGG_BLOCKS = (int)((NWARPS * 32 + T - 1) / T);

    // host-side objects only (no device allocation); leaked intentionally —
    // kernel_launch runs O(1) times
    cudaStream_t s2;
    cudaStreamCreate(&s2);
    cudaEvent_t eFork, eH;
    cudaEventCreateWithFlags(&eFork, cudaEventDisableTiming);
    cudaEventCreateWithFlags(&eH,    cudaEventDisableTiming);

    // fork: CSR build (self-initializing) runs concurrently with gemm1
    cudaEventRecord(eFork, 0);
    cudaStreamWaitEvent(s2, eFork, 0);
    histscan_kernel<<<NB_SCAN, 1024, 0, s2>>>(ei);
    cudaEventRecord(eH, s2);

    gemm1_kernel<<<(NN + G1_ROWS - 1) / G1_ROWS, 256>>>(x, W1, att_src1, att_dst1);

    cudaStreamWaitEvent(0, eH, 0);
    agg1_kernel<<<AGG_BLOCKS, T>>>(b1);
    gemm2_kernel<<<(NN + G2_ROWS - 1) / G2_ROWS, 256>>>(W2, att_src2, att_dst2);
    agg2_kernel<<<AGG_BLOCKS, T>>>(dout, b2);
}

// round 15
// speedup vs baseline: 1.1344x; 1.0258x over previous
#include <cuda_runtime.h>
#include <cuda_fp16.h>
#include <math.h>

// ---------------- problem constants ----------------
#define NN   100000
#define EE0  1600000            // raw edges
#define EETOT (EE0 + NN)        // + self loops
#define C1   64                 // in channels
#define H1   4                  // heads layer1
#define HC1  128                // H1*D1
#define OUTC 32                 // layer2 out channels
#define NB_SCAN 98              // ceil(NN/1024)
#define LOG2E 1.4426950408889634f

typedef unsigned long long u64;
#define FMA_X2(d, a, b, c) \
    asm("fma.rn.f32x2 %0, %1, %2, %3;" : "=l"(d) : "l"(a), "l"(b), "l"(c))
#define PACK2(d, lo, hi) \
    asm("mov.b64 %0, {%1, %2};" : "=l"(d) : "f"(lo), "f"(hi))
#define UNPACK2(lo, hi, s) \
    asm("mov.b64 {%0, %1}, %2;" : "=f"(lo), "=f"(hi) : "l"(s))

union F4U2 { float4 f4; u64 u[2]; };

// ---------------- scratch (device globals; no allocation) ----------------
__device__ __half g_h1h[NN * HC1];      // layer1 features (fp16, gather-only)
__device__ __half g_out1h[NN * HC1];    // elu(agg1 + b1) (fp16, gemm2 input)
__device__ float  g_al_src1[NN * H1];   // pre-scaled by log2(e)
__device__ float  g_al_dst1[NN * H1];

__device__ float  g_h2f[NN * OUTC];     // layer2 features (fp32, L2-resident)
__device__ float  g_al_src2[NN];        // pre-scaled by log2(e)
__device__ float  g_al_dst2[NN];

// CSR build
__device__ int g_deg[NN];
__device__ int g_cursor[NN];
__device__ int g_bsum[NB_SCAN];
__device__ int g_boff[NB_SCAN];
__device__ int g_off[NN + 1];
__device__ int g_esrc[EETOT];
// monotonic handoff counters [cnt,rel] x 4 — NEVER reset (BSS-zeroed at load)
__device__ int g_sync[8];

// ---------------- helpers ----------------
__device__ __forceinline__ float ex2(float x) {
    float r;
    asm("ex2.approx.ftz.f32 %0, %1;" : "=f"(r) : "f"(x));
    return r;
}
// weight from pre-scaled logit sum: 2^(leaky(x))
__device__ __forceinline__ float wfun(float x) {
    return ex2(fmaxf(x, 0.2f * x));
}

// int64 little-endian edges => int32 view has zero high words (indices < 2^31)
__device__ __forceinline__ int detect_is64(const int* __restrict__ ei) {
    int zeros = 0;
#pragma unroll
    for (int k = 0; k < 16; k++) zeros += (ei[2 * k + 1] == 0);
    return zeros == 16;
}

// monotonic grid-wide handoff among NB_SCAN resident blocks
__device__ __forceinline__ void mono_handoff(int idx) {
    __syncthreads();
    if (threadIdx.x == 0) {
        __threadfence();
        int tk = atomicAdd(&g_sync[2 * idx], 1);
        int g = tk / NB_SCAN;
        if ((tk % NB_SCAN) == NB_SCAN - 1) atomicAdd(&g_sync[2 * idx + 1], 1);
        while (atomicAdd(&g_sync[2 * idx + 1], 0) < g + 1) { }
        __threadfence();
    }
    __syncthreads();
}

// ---------------- GEMM1 + fused logits1 ----------------
#define G1_ROWS 64
__global__ __launch_bounds__(256) void gemm1_kernel(const float* __restrict__ x,
                                                    const float* __restrict__ W,
                                                    const float* __restrict__ asrc,
                                                    const float* __restrict__ adst) {
    __shared__ float xst[C1][G1_ROWS];   // [k][row] 16 KB
    __shared__ float Ws[C1][HC1];        // 32 KB
    int tid = threadIdx.x;
    int row0 = blockIdx.x * G1_ROWS;

    const float4* W4 = (const float4*)W;
    float4* Ws4 = (float4*)Ws;
#pragma unroll
    for (int i = 0; i < 8; i++) Ws4[tid + 256 * i] = W4[tid + 256 * i];
#pragma unroll
    for (int i = 0; i < 4; i++) {
        int idx = tid + 256 * i;          // float4 idx; 16 per row
        int r = idx >> 4, k4 = idx & 15;
        int row = row0 + r;
        float4 v = make_float4(0.f, 0.f, 0.f, 0.f);
        if (row < NN) v = *(const float4*)&x[row * C1 + k4 * 4];
        xst[k4 * 4 + 0][r] = v.x; xst[k4 * 4 + 1][r] = v.y;
        xst[k4 * 4 + 2][r] = v.z; xst[k4 * 4 + 3][r] = v.w;
    }
    __syncthreads();

    int lane = tid & 31, w = tid >> 5;
    int rb = w * 8;
    u64 acc2[4][4];                     // [row-pair][col]
#pragma unroll
    for (int m = 0; m < 4; m++)
#pragma unroll
        for (int c = 0; c < 4; c++) acc2[m][c] = 0ull;

#pragma unroll
    for (int k = 0; k < C1; k++) {
        F4U2 xa, xb;
        xa.f4 = *(float4*)&xst[k][rb];
        xb.f4 = *(float4*)&xst[k][rb + 4];
        float4 wv = *(float4*)&Ws[k][lane * 4];
        u64 wd[4];
        PACK2(wd[0], wv.x, wv.x); PACK2(wd[1], wv.y, wv.y);
        PACK2(wd[2], wv.z, wv.z); PACK2(wd[3], wv.w, wv.w);
        u64 xp[4] = {xa.u[0], xa.u[1], xb.u[0], xb.u[1]};
#pragma unroll
        for (int m = 0; m < 4; m++) {
            FMA_X2(acc2[m][0], xp[m], wd[0], acc2[m][0]);
            FMA_X2(acc2[m][1], xp[m], wd[1], acc2[m][1]);
            FMA_X2(acc2[m][2], xp[m], wd[2], acc2[m][2]);
            FMA_X2(acc2[m][3], xp[m], wd[3], acc2[m][3]);
        }
    }

    float acc[8][4];
#pragma unroll
    for (int m = 0; m < 4; m++)
#pragma unroll
        for (int c = 0; c < 4; c++)
            UNPACK2(acc[2 * m][c], acc[2 * m + 1][c], acc2[m][c]);

    float4 av = *(const float4*)&asrc[lane * 4];
    float4 bv = *(const float4*)&adst[lane * 4];
    int head = lane >> 3;
#pragma unroll
    for (int r = 0; r < 8; r++) {
        int row = row0 + rb + r;
        if (row < NN) {
            __half2 p0 = __floats2half2_rn(acc[r][0], acc[r][1]);
            __half2 p1 = __floats2half2_rn(acc[r][2], acc[r][3]);
            uint2 u;
            u.x = *reinterpret_cast<unsigned*>(&p0);
            u.y = *reinterpret_cast<unsigned*>(&p1);
            *reinterpret_cast<uint2*>(&g_h1h[row * HC1 + lane * 4]) = u;
        }
        float ps = acc[r][0] * av.x + acc[r][1] * av.y + acc[r][2] * av.z + acc[r][3] * av.w;
        float pd = acc[r][0] * bv.x + acc[r][1] * bv.y + acc[r][2] * bv.z + acc[r][3] * bv.w;
#pragma unroll
        for (int off = 4; off >= 1; off >>= 1) {
            ps += __shfl_down_sync(0xffffffffu, ps, off);
            pd += __shfl_down_sync(0xffffffffu, pd, off);
        }
        if ((lane & 7) == 0 && row < NN) {
            g_al_src1[row * H1 + head] = ps * LOG2E;
            g_al_dst1[row * H1 + head] = pd * LOG2E;
        }
    }
}

// ---------------- zero + hist + scan + scatter: one persistent kernel -------
__global__ __launch_bounds__(1024) void histscan_kernel(const int* __restrict__ ei) {
    __shared__ int warp_tot[32];
    __shared__ int block_base;
    __shared__ int sh_is64;
    int t = threadIdx.x;
    int i = blockIdx.x * 1024 + t;
    int lane = t & 31, w = t >> 5;
    if (t == 0) sh_is64 = detect_is64(ei);

    // ---- phase -1: zero deg (self-init) ----
    for (int n = blockIdx.x * 1024 + t; n < NN; n += NB_SCAN * 1024)
        g_deg[n] = 0;
    __syncthreads();
    int is64 = sh_is64;
    mono_handoff(0);                    // all zeros visible

    // ---- phase 0: dst histogram (grid-stride) ----
    for (int e = blockIdx.x * 1024 + t; e < EETOT; e += NB_SCAN * 1024) {
        int d;
        if (e >= EE0) d = e - EE0;
        else d = is64 ? ei[2 * (EE0 + e)] : ei[EE0 + e];
        atomicAdd(&g_deg[d], 1);
    }
    mono_handoff(1);                    // all histogram atomics visible

    // ---- phase 1: scan ----
    int deg = (i < NN) ? g_deg[i] : 0;
    int sum = deg;
#pragma unroll
    for (int o = 1; o < 32; o <<= 1) {
        int u = __shfl_up_sync(0xffffffffu, sum, o);
        if (lane >= o) sum += u;
    }
    if (lane == 31) warp_tot[w] = sum;
    __syncthreads();
    if (w == 0) {
        int s = warp_tot[lane];
#pragma unroll
        for (int o = 1; o < 32; o <<= 1) {
            int u = __shfl_up_sync(0xffffffffu, s, o);
            if (lane >= o) s += u;
        }
        warp_tot[lane] = s;
    }
    __syncthreads();
    int wbase = (w > 0) ? warp_tot[w - 1] : 0;
    int inc = wbase + sum;              // inclusive scan within block
    if (t == 1023) g_bsum[blockIdx.x] = inc;
    __syncthreads();                    // bsum written before ticket

    // handoff (custom): last-arriving block's warp 0 scans the block sums
    if (w == 0) {
        int tk = 0;
        if (lane == 0) {
            __threadfence();
            tk = atomicAdd(&g_sync[4], 1);
        }
        tk = __shfl_sync(0xffffffffu, tk, 0);
        int gen = tk / NB_SCAN;
        if ((tk % NB_SCAN) == NB_SCAN - 1) {
            int carry = 0;
#pragma unroll
            for (int c = 0; c < 4; c++) {
                int idx = c * 32 + lane;
                int v = (idx < NB_SCAN) ? g_bsum[idx] : 0;
                int s = v;
#pragma unroll
                for (int o = 1; o < 32; o <<= 1) {
                    int u = __shfl_up_sync(0xffffffffu, s, o);
                    if (lane >= o) s += u;
                }
                if (idx < NB_SCAN) g_boff[idx] = carry + s - v;   // exclusive
                carry += __shfl_sync(0xffffffffu, s, 31);
            }
            __threadfence();
            if (lane == 0) atomicAdd(&g_sync[5], 1);
        }
        if (lane == 0) {
            while (atomicAdd(&g_sync[5], 0) < gen + 1) { }
            __threadfence();
            block_base = g_boff[blockIdx.x];
        }
    }
    __syncthreads();
    int base = block_base;
    if (i == 0) g_off[0] = 0;
    if (i < NN) {
        int end = base + inc;
        g_off[i + 1] = end;
        g_cursor[i] = end - deg;        // start offset; scatter bumps this
    }
    mono_handoff(3);                    // all cursors visible before scatter

    // ---- phase 2: scatter (grid-stride) ----
    for (int e = blockIdx.x * 1024 + t; e < EETOT; e += NB_SCAN * 1024) {
        int s, d;
        if (e >= EE0) { s = d = e - EE0; }
        else if (is64) { s = ei[2 * e]; d = ei[2 * (EE0 + e)]; }
        else           { s = ei[e];     d = ei[EE0 + e]; }
        int pos = atomicAdd(&g_cursor[d], 1);
        g_esrc[pos] = s;
    }
}

// ---------------- fused agg1: HALF-warp per dst node (2 nodes/warp) ---------
// lane = half*16 + sl; sl covers channels [sl*8, sl*8+8) as uint4 of half2s
__global__ void agg1_kernel(const float* __restrict__ b1) {
    int gid = blockIdx.x * blockDim.x + threadIdx.x;
    int wid = gid >> 5;
    int lane = gid & 31;
    int half = lane >> 4;
    int sl = lane & 15;
    int d = wid * 2 + half;
    if (d >= NN) return;
    int h = sl >> 2;                     // head = channel/32
    int ch0 = sl * 8;
    const float* __restrict__ als = g_al_src1;
    const int* __restrict__ esrc = g_esrc;
    const __half* __restrict__ h1p = g_h1h;
    float adh = g_al_dst1[d * H1 + h];
    int j0 = g_off[d], j1 = g_off[d + 1];
    float acc[8];
#pragma unroll
    for (int q = 0; q < 8; q++) acc[q] = 0.f;
    float den = 0.f;
    int j = j0;
    for (; j + 1 < j1; j += 2) {
        int s0 = esrc[j], s1 = esrc[j + 1];
        float x0 = als[s0 * H1 + h] + adh;
        float x1 = als[s1 * H1 + h] + adh;
        uint4 v0 = *reinterpret_cast<const uint4*>(&h1p[s0 * HC1 + ch0]);
        uint4 v1 = *reinterpret_cast<const uint4*>(&h1p[s1 * HC1 + ch0]);
        float w0 = wfun(x0), w1 = wfun(x1);
        den += w0 + w1;
        const unsigned u0[4] = {v0.x, v0.y, v0.z, v0.w};
        const unsigned u1[4] = {v1.x, v1.y, v1.z, v1.w};
#pragma unroll
        for (int q = 0; q < 4; q++) {
            float2 f0 = __half22float2(*reinterpret_cast<const __half2*>(&u0[q]));
            float2 f1 = __half22float2(*reinterpret_cast<const __half2*>(&u1[q]));
            acc[2 * q + 0] += w0 * f0.x + w1 * f1.x;
            acc[2 * q + 1] += w0 * f0.y + w1 * f1.y;
        }
    }
    if (j < j1) {
        int s0 = esrc[j];
        float x0 = als[s0 * H1 + h] + adh;
        uint4 v0 = *reinterpret_cast<const uint4*>(&h1p[s0 * HC1 + ch0]);
        float w0 = wfun(x0);
        den += w0;
        const unsigned u0[4] = {v0.x, v0.y, v0.z, v0.w};
#pragma unroll
        for (int q = 0; q < 4; q++) {
            float2 f0 = __half22float2(*reinterpret_cast<const __half2*>(&u0[q]));
            acc[2 * q + 0] += w0 * f0.x;
            acc[2 * q + 1] += w0 * f0.y;
        }
    }
    float inv = 1.f / den;               // self-loop guarantees den > 0
    float4 ba = *reinterpret_cast<const float4*>(&b1[ch0]);
    float4 bb = *reinterpret_cast<const float4*>(&b1[ch0 + 4]);
    float ob[8];
    ob[0] = acc[0] * inv + ba.x; ob[1] = acc[1] * inv + ba.y;
    ob[2] = acc[2] * inv + ba.z; ob[3] = acc[3] * inv + ba.w;
    ob[4] = acc[4] * inv + bb.x; ob[5] = acc[5] * inv + bb.y;
    ob[6] = acc[6] * inv + bb.z; ob[7] = acc[7] * inv + bb.w;
#pragma unroll
    for (int q = 0; q < 8; q++) ob[q] = ob[q] > 0.f ? ob[q] : expm1f(ob[q]);
    uint4 o;
    __half2 p0 = __floats2half2_rn(ob[0], ob[1]);
    __half2 p1 = __floats2half2_rn(ob[2], ob[3]);
    __half2 p2 = __floats2half2_rn(ob[4], ob[5]);
    __half2 p3 = __floats2half2_rn(ob[6], ob[7]);
    o.x = *reinterpret_cast<unsigned*>(&p0);
    o.y = *reinterpret_cast<unsigned*>(&p1);
    o.z = *reinterpret_cast<unsigned*>(&p2);
    o.w = *reinterpret_cast<unsigned*>(&p3);
    *reinterpret_cast<uint4*>(&g_out1h[d * HC1 + ch0]) = o;
}

// ---------------- GEMM2 + fused logits2 (8 rows x 4 cols per thread) --------
#define G2_ROWS 256
#define G2_PAD  260
__global__ __launch_bounds__(256) void gemm2_kernel(const float* __restrict__ W2,
                                                    const float* __restrict__ asrc,
                                                    const float* __restrict__ adst) {
    __shared__ float xst[32][G2_PAD];    // ~33.3 KB  [k][row]
    __shared__ float Wc[32][OUTC];       // 4 KB      [k][col] (current K-chunk)
    int tid = threadIdx.x;
    int row0 = blockIdx.x * G2_ROWS;
    int lane = tid & 31, w = tid >> 5;
    int row_sub = lane >> 3;             // 0..3
    int cg = lane & 7;                   // 0..7
    int rbase = w * 32 + row_sub * 8;    // 8 consecutive rows per thread

    u64 acc2[4][4];                      // [row-pair][col]
#pragma unroll
    for (int m = 0; m < 4; m++)
#pragma unroll
        for (int c = 0; c < 4; c++) acc2[m][c] = 0ull;

#pragma unroll
    for (int kc = 0; kc < 4; kc++) {
        {
            const float4* Wg = (const float4*)(W2 + kc * 32 * OUTC);
            ((float4*)Wc)[tid] = Wg[tid];
        }
#pragma unroll
        for (int i = 0; i < 4; i++) {
            int idx = tid + 256 * i;     // 0..1023
            int k8 = idx >> 8;           // 0..3
            int row = idx & 255;
            int grow = row0 + row;
            uint4 v = make_uint4(0u, 0u, 0u, 0u);
            if (grow < NN) v = *(const uint4*)&g_out1h[grow * HC1 + kc * 32 + k8 * 8];
            const unsigned uu[4] = {v.x, v.y, v.z, v.w};
#pragma unroll
            for (int q = 0; q < 4; q++) {
                __half2 hh = *reinterpret_cast<const __half2*>(&uu[q]);
                float2 ff = __half22float2(hh);
                xst[k8 * 8 + q * 2 + 0][row] = ff.x;
                xst[k8 * 8 + q * 2 + 1][row] = ff.y;
            }
        }
        __syncthreads();

#pragma unroll 8
        for (int k = 0; k < 32; k++) {
            F4U2 xa, xb;
            xa.f4 = *(float4*)&xst[k][rbase];          // rows 0..3
            xb.f4 = *(float4*)&xst[k][rbase + 4];      // rows 4..7
            float4 wv = *(float4*)&Wc[k][cg * 4];      // 4 cols
            u64 wd0, wd1, wd2, wd3;
            PACK2(wd0, wv.x, wv.x); PACK2(wd1, wv.y, wv.y);
            PACK2(wd2, wv.z, wv.z); PACK2(wd3, wv.w, wv.w);
            u64 xp[4] = {xa.u[0], xa.u[1], xb.u[0], xb.u[1]};
#pragma unroll
            for (int m = 0; m < 4; m++) {
                FMA_X2(acc2[m][0], xp[m], wd0, acc2[m][0]);
                FMA_X2(acc2[m][1], xp[m], wd1, acc2[m][1]);
                FMA_X2(acc2[m][2], xp[m], wd2, acc2[m][2]);
                FMA_X2(acc2[m][3], xp[m], wd3, acc2[m][3]);
            }
        }
        __syncthreads();
    }

    float acc[8][4];                     // [row][col]
#pragma unroll
    for (int m = 0; m < 4; m++)
#pragma unroll
        for (int c = 0; c < 4; c++)
            UNPACK2(acc[2 * m][c], acc[2 * m + 1][c], acc2[m][c]);

    float4 av = *(const float4*)&asrc[cg * 4];
    float4 bv = *(const float4*)&adst[cg * 4];
#pragma unroll
    for (int r = 0; r < 8; r++) {
        int row = row0 + rbase + r;
        if (row < NN)
            *(float4*)&g_h2f[row * OUTC + cg * 4] = *(float4*)acc[r];
        float ps = acc[r][0] * av.x + acc[r][1] * av.y + acc[r][2] * av.z + acc[r][3] * av.w;
        float pd = acc[r][0] * bv.x + acc[r][1] * bv.y + acc[r][2] * bv.z + acc[r][3] * bv.w;
#pragma unroll
        for (int off = 4; off >= 1; off >>= 1) {
            ps += __shfl_down_sync(0xffffffffu, ps, off);
            pd += __shfl_down_sync(0xffffffffu, pd, off);
        }
        if (cg == 0 && row < NN) {
            g_al_src2[row] = ps * LOG2E;
            g_al_dst2[row] = pd * LOG2E;
        }
    }
}

// ---------------- fused agg2: QUARTER-warp per dst node (4 nodes/warp) ------
// lane = q*8 + sl; node q in 0..3; sl covers channels [sl*4, sl*4+4) as float4
__global__ void agg2_kernel(float* __restrict__ dout, const float* __restrict__ b2) {
    int gid = blockIdx.x * blockDim.x + threadIdx.x;
    int wid = gid >> 5;
    int lane = gid & 31;
    int q = lane >> 3;
    int sl = lane & 7;
    int d = wid * 4 + q;
    if (d >= NN) return;
    int ch0 = sl * 4;
    const float* __restrict__ als = g_al_src2;
    const int* __restrict__ esrc = g_esrc;
    const float* __restrict__ h2p = g_h2f;
    float ad2 = g_al_dst2[d];
    int j0 = g_off[d], j1 = g_off[d + 1];
    float4 acc = make_float4(0.f, 0.f, 0.f, 0.f);
    float den = 0.f;
    int j = j0;
    for (; j + 1 < j1; j += 2) {
        int s0 = esrc[j], s1 = esrc[j + 1];
        float x0 = als[s0] + ad2;
        float x1 = als[s1] + ad2;
        float4 v0 = *reinterpret_cast<const float4*>(&h2p[s0 * OUTC + ch0]);
        float4 v1 = *reinterpret_cast<const float4*>(&h2p[s1 * OUTC + ch0]);
        float w0 = wfun(x0), w1 = wfun(x1);
        den += w0 + w1;
        acc.x += w0 * v0.x + w1 * v1.x;
        acc.y += w0 * v0.y + w1 * v1.y;
        acc.z += w0 * v0.z + w1 * v1.z;
        acc.w += w0 * v0.w + w1 * v1.w;
    }
    if (j < j1) {
        int s0 = esrc[j];
        float w0 = wfun(als[s0] + ad2);
        float4 v0 = *reinterpret_cast<const float4*>(&h2p[s0 * OUTC + ch0]);
        den += w0;
        acc.x += w0 * v0.x; acc.y += w0 * v0.y;
        acc.z += w0 * v0.z; acc.w += w0 * v0.w;
    }
    float inv = 1.f / den;
    float4 bb = *reinterpret_cast<const float4*>(&b2[ch0]);
    float4 o;
    o.x = acc.x * inv + bb.x;
    o.y = acc.y * inv + bb.y;
    o.z = acc.z * inv + bb.z;
    o.w = acc.w * inv + bb.w;
    *reinterpret_cast<float4*>(&dout[d * OUTC + ch0]) = o;
}

// ---------------- launch ----------------
extern "C" void kernel_launch(void* const* d_in, const int* in_sizes, int n_in,
                              void* d_out, int out_size) {
    const float* x        = (const float*)d_in[0];
    const int*   ei       = (const int*)d_in[1];
    const float* W1       = (const float*)d_in[2];
    const float* att_src1 = (const float*)d_in[3];
    const float* att_dst1 = (const float*)d_in[4];
    const float* b1       = (const float*)d_in[5];
    const float* W2       = (const float*)d_in[6];
    const float* att_src2 = (const float*)d_in[7];
    const float* att_dst2 = (const float*)d_in[8];
    const float* b2       = (const float*)d_in[9];
    float* dout = (float*)d_out;

    const int T = 256;
    const long NW1 = (NN + 1) / 2;              // agg1: 2 nodes per warp
    const int AGG1_BLOCKS = (int)((NW1 * 32 + T - 1) / T);
    const long NW2 = (NN + 3) / 4;              // agg2: 4 nodes per warp
    const int AGG2_BLOCKS = (int)((NW2 * 32 + T - 1) / T);

    // host-side objects only (no device allocation); leaked intentionally —
    // kernel_launch runs O(1) times
    cudaStream_t s2;
    cudaStreamCreate(&s2);
    cudaEvent_t eFork, eH;
    cudaEventCreateWithFlags(&eFork, cudaEventDisableTiming);
    cudaEventCreateWithFlags(&eH,    cudaEventDisableTiming);

    // fork: CSR build (self-initializing) runs concurrently with gemm1
    cudaEventRecord(eFork, 0);
    cudaStreamWaitEvent(s2, eFork, 0);
    histscan_kernel<<<NB_SCAN, 1024, 0, s2>>>(ei);
    cudaEventRecord(eH, s2);

    gemm1_kernel<<<(NN + G1_ROWS - 1) / G1_ROWS, 256>>>(x, W1, att_src1, att_dst1);

    cudaStreamWaitEvent(0, eH, 0);
    agg1_kernel<<<AGG1_BLOCKS, T>>>(b1);
    gemm2_kernel<<<(NN + G2_ROWS - 1) / G2_ROWS, 256>>>(W2, att_src2, att_dst2);
    agg2_kernel<<<AGG2_BLOCKS, T>>>(dout, b2);
}

// round 16
// speedup vs baseline: 1.1355x; 1.0010x over previous
#include <cuda_runtime.h>
#include <cuda_fp16.h>
#include <math.h>

// ---------------- problem constants ----------------
#define NN   100000
#define EE0  1600000            // raw edges
#define EETOT (EE0 + NN)        // + self loops
#define C1   64                 // in channels
#define H1   4                  // heads layer1
#define HC1  128                // H1*D1
#define OUTC 32                 // layer2 out channels
#define NB_SCAN 98              // ceil(NN/1024)
#define LOG2E 1.4426950408889634f

typedef unsigned long long u64;
#define FMA_X2(d, a, b, c) \
    asm("fma.rn.f32x2 %0, %1, %2, %3;" : "=l"(d) : "l"(a), "l"(b), "l"(c))
#define PACK2(d, lo, hi) \
    asm("mov.b64 %0, {%1, %2};" : "=l"(d) : "f"(lo), "f"(hi))
#define UNPACK2(lo, hi, s) \
    asm("mov.b64 {%0, %1}, %2;" : "=f"(lo), "=f"(hi) : "l"(s))

union F4U2 { float4 f4; u64 u[2]; };

// ---------------- scratch (device globals; no allocation) ----------------
__device__ __half g_h1h[NN * HC1];      // layer1 features (fp16, gather-only)
__device__ __half g_out1h[NN * HC1];    // elu(agg1 + b1) (fp16, gemm2 input)
__device__ float  g_al_src1[NN * H1];   // pre-scaled by log2(e)
__device__ float  g_al_dst1[NN * H1];

__device__ float  g_h2f[NN * OUTC];     // layer2 features (fp32, L2-resident)
__device__ float  g_al_src2[NN];        // pre-scaled by log2(e)
__device__ float  g_al_dst2[NN];

// CSR build
__device__ int g_deg[NN];
__device__ int g_cursor[NN];
__device__ int g_bsum[NB_SCAN];
__device__ int g_boff[NB_SCAN];
__device__ int g_off[NN + 1];
__device__ int g_esrc[EETOT];
// monotonic handoff counters [cnt,rel] x 4 — NEVER reset (BSS-zeroed at load)
__device__ int g_sync[8];

// ---------------- helpers ----------------
__device__ __forceinline__ float ex2(float x) {
    float r;
    asm("ex2.approx.ftz.f32 %0, %1;" : "=f"(r) : "f"(x));
    return r;
}
// weight from pre-scaled logit sum: 2^(leaky(x))
__device__ __forceinline__ float wfun(float x) {
    return ex2(fmaxf(x, 0.2f * x));
}

// int64 little-endian edges => int32 view has zero high words (indices < 2^31)
__device__ __forceinline__ int detect_is64(const int* __restrict__ ei) {
    int zeros = 0;
#pragma unroll
    for (int k = 0; k < 16; k++) zeros += (ei[2 * k + 1] == 0);
    return zeros == 16;
}

// monotonic grid-wide handoff among NB_SCAN resident blocks
__device__ __forceinline__ void mono_handoff(int idx) {
    __syncthreads();
    if (threadIdx.x == 0) {
        __threadfence();
        int tk = atomicAdd(&g_sync[2 * idx], 1);
        int g = tk / NB_SCAN;
        if ((tk % NB_SCAN) == NB_SCAN - 1) atomicAdd(&g_sync[2 * idx + 1], 1);
        while (atomicAdd(&g_sync[2 * idx + 1], 0) < g + 1) { }
        __threadfence();
    }
    __syncthreads();
}

// ---------------- GEMM1 + fused logits1 ----------------
#define G1_ROWS 64
__global__ __launch_bounds__(256) void gemm1_kernel(const float* __restrict__ x,
                                                    const float* __restrict__ W,
                                                    const float* __restrict__ asrc,
                                                    const float* __restrict__ adst) {
    __shared__ float xst[C1][G1_ROWS];   // [k][row] 16 KB
    __shared__ float Ws[C1][HC1];        // 32 KB
    int tid = threadIdx.x;
    int row0 = blockIdx.x * G1_ROWS;

    const float4* W4 = (const float4*)W;
    float4* Ws4 = (float4*)Ws;
#pragma unroll
    for (int i = 0; i < 8; i++) Ws4[tid + 256 * i] = W4[tid + 256 * i];
#pragma unroll
    for (int i = 0; i < 4; i++) {
        int idx = tid + 256 * i;          // float4 idx; 16 per row
        int r = idx >> 4, k4 = idx & 15;
        int row = row0 + r;
        float4 v = make_float4(0.f, 0.f, 0.f, 0.f);
        if (row < NN) v = *(const float4*)&x[row * C1 + k4 * 4];
        xst[k4 * 4 + 0][r] = v.x; xst[k4 * 4 + 1][r] = v.y;
        xst[k4 * 4 + 2][r] = v.z; xst[k4 * 4 + 3][r] = v.w;
    }
    __syncthreads();

    int lane = tid & 31, w = tid >> 5;
    int rb = w * 8;
    u64 acc2[4][4];                     // [row-pair][col]
#pragma unroll
    for (int m = 0; m < 4; m++)
#pragma unroll
        for (int c = 0; c < 4; c++) acc2[m][c] = 0ull;

#pragma unroll
    for (int k = 0; k < C1; k++) {
        F4U2 xa, xb;
        xa.f4 = *(float4*)&xst[k][rb];
        xb.f4 = *(float4*)&xst[k][rb + 4];
        float4 wv = *(float4*)&Ws[k][lane * 4];
        u64 wd[4];
        PACK2(wd[0], wv.x, wv.x); PACK2(wd[1], wv.y, wv.y);
        PACK2(wd[2], wv.z, wv.z); PACK2(wd[3], wv.w, wv.w);
        u64 xp[4] = {xa.u[0], xa.u[1], xb.u[0], xb.u[1]};
#pragma unroll
        for (int m = 0; m < 4; m++) {
            FMA_X2(acc2[m][0], xp[m], wd[0], acc2[m][0]);
            FMA_X2(acc2[m][1], xp[m], wd[1], acc2[m][1]);
            FMA_X2(acc2[m][2], xp[m], wd[2], acc2[m][2]);
            FMA_X2(acc2[m][3], xp[m], wd[3], acc2[m][3]);
        }
    }

    float acc[8][4];
#pragma unroll
    for (int m = 0; m < 4; m++)
#pragma unroll
        for (int c = 0; c < 4; c++)
            UNPACK2(acc[2 * m][c], acc[2 * m + 1][c], acc2[m][c]);

    float4 av = *(const float4*)&asrc[lane * 4];
    float4 bv = *(const float4*)&adst[lane * 4];
    int head = lane >> 3;
#pragma unroll
    for (int r = 0; r < 8; r++) {
        int row = row0 + rb + r;
        if (row < NN) {
            __half2 p0 = __floats2half2_rn(acc[r][0], acc[r][1]);
            __half2 p1 = __floats2half2_rn(acc[r][2], acc[r][3]);
            uint2 u;
            u.x = *reinterpret_cast<unsigned*>(&p0);
            u.y = *reinterpret_cast<unsigned*>(&p1);
            *reinterpret_cast<uint2*>(&g_h1h[row * HC1 + lane * 4]) = u;
        }
        float ps = acc[r][0] * av.x + acc[r][1] * av.y + acc[r][2] * av.z + acc[r][3] * av.w;
        float pd = acc[r][0] * bv.x + acc[r][1] * bv.y + acc[r][2] * bv.z + acc[r][3] * bv.w;
#pragma unroll
        for (int off = 4; off >= 1; off >>= 1) {
            ps += __shfl_down_sync(0xffffffffu, ps, off);
            pd += __shfl_down_sync(0xffffffffu, pd, off);
        }
        if ((lane & 7) == 0 && row < NN) {
            g_al_src1[row * H1 + head] = ps * LOG2E;
            g_al_dst1[row * H1 + head] = pd * LOG2E;
        }
    }
}

// ---------------- zero + hist + scan + scatter: one persistent kernel -------
__global__ __launch_bounds__(1024) void histscan_kernel(const int* __restrict__ ei) {
    __shared__ int warp_tot[32];
    __shared__ int block_base;
    __shared__ int sh_is64;
    int t = threadIdx.x;
    int i = blockIdx.x * 1024 + t;
    int lane = t & 31, w = t >> 5;
    if (t == 0) sh_is64 = detect_is64(ei);

    // ---- phase -1: zero deg (self-init) ----
    for (int n = blockIdx.x * 1024 + t; n < NN; n += NB_SCAN * 1024)
        g_deg[n] = 0;
    __syncthreads();
    int is64 = sh_is64;
    mono_handoff(0);                    // all zeros visible

    // ---- phase 0: dst histogram (grid-stride) ----
    for (int e = blockIdx.x * 1024 + t; e < EETOT; e += NB_SCAN * 1024) {
        int d;
        if (e >= EE0) d = e - EE0;
        else d = is64 ? ei[2 * (EE0 + e)] : ei[EE0 + e];
        atomicAdd(&g_deg[d], 1);
    }
    mono_handoff(1);                    // all histogram atomics visible

    // ---- phase 1: scan ----
    int deg = (i < NN) ? g_deg[i] : 0;
    int sum = deg;
#pragma unroll
    for (int o = 1; o < 32; o <<= 1) {
        int u = __shfl_up_sync(0xffffffffu, sum, o);
        if (lane >= o) sum += u;
    }
    if (lane == 31) warp_tot[w] = sum;
    __syncthreads();
    if (w == 0) {
        int s = warp_tot[lane];
#pragma unroll
        for (int o = 1; o < 32; o <<= 1) {
            int u = __shfl_up_sync(0xffffffffu, s, o);
            if (lane >= o) s += u;
        }
        warp_tot[lane] = s;
    }
    __syncthreads();
    int wbase = (w > 0) ? warp_tot[w - 1] : 0;
    int inc = wbase + sum;              // inclusive scan within block
    if (t == 1023) g_bsum[blockIdx.x] = inc;
    __syncthreads();                    // bsum written before ticket

    // handoff (custom): last-arriving block's warp 0 scans the block sums
    if (w == 0) {
        int tk = 0;
        if (lane == 0) {
            __threadfence();
            tk = atomicAdd(&g_sync[4], 1);
        }
        tk = __shfl_sync(0xffffffffu, tk, 0);
        int gen = tk / NB_SCAN;
        if ((tk % NB_SCAN) == NB_SCAN - 1) {
            int carry = 0;
#pragma unroll
            for (int c = 0; c < 4; c++) {
                int idx = c * 32 + lane;
                int v = (idx < NB_SCAN) ? g_bsum[idx] : 0;
                int s = v;
#pragma unroll
                for (int o = 1; o < 32; o <<= 1) {
                    int u = __shfl_up_sync(0xffffffffu, s, o);
                    if (lane >= o) s += u;
                }
                if (idx < NB_SCAN) g_boff[idx] = carry + s - v;   // exclusive
                carry += __shfl_sync(0xffffffffu, s, 31);
            }
            __threadfence();
            if (lane == 0) atomicAdd(&g_sync[5], 1);
        }
        if (lane == 0) {
            while (atomicAdd(&g_sync[5], 0) < gen + 1) { }
            __threadfence();
            block_base = g_boff[blockIdx.x];
        }
    }
    __syncthreads();
    int base = block_base;
    if (i == 0) g_off[0] = 0;
    if (i < NN) {
        int end = base + inc;
        g_off[i + 1] = end;
        g_cursor[i] = end - deg;        // start offset; scatter bumps this
    }
    mono_handoff(3);                    // all cursors visible before scatter

    // ---- phase 2: scatter (grid-stride) ----
    for (int e = blockIdx.x * 1024 + t; e < EETOT; e += NB_SCAN * 1024) {
        int s, d;
        if (e >= EE0) { s = d = e - EE0; }
        else if (is64) { s = ei[2 * e]; d = ei[2 * (EE0 + e)]; }
        else           { s = ei[e];     d = ei[EE0 + e]; }
        int pos = atomicAdd(&g_cursor[d], 1);
        g_esrc[pos] = s;
    }
}

// ---------------- fused agg1: HALF-warp per dst node (2 nodes/warp) ---------
// lane = half*16 + sl; sl covers channels [sl*8, sl*8+8) as uint4 of half2s
__global__ void agg1_kernel(const float* __restrict__ b1) {
    int gid = blockIdx.x * blockDim.x + threadIdx.x;
    int wid = gid >> 5;
    int lane = gid & 31;
    int half = lane >> 4;
    int sl = lane & 15;
    int d = wid * 2 + half;
    if (d >= NN) return;
    int h = sl >> 2;                     // head = channel/32
    int ch0 = sl * 8;
    const float* __restrict__ als = g_al_src1;
    const int* __restrict__ esrc = g_esrc;
    const __half* __restrict__ h1p = g_h1h;
    float adh = g_al_dst1[d * H1 + h];
    int j0 = g_off[d], j1 = g_off[d + 1];
    float acc[8];
#pragma unroll
    for (int q = 0; q < 8; q++) acc[q] = 0.f;
    float den = 0.f;
    int j = j0;
    for (; j + 1 < j1; j += 2) {
        int s0 = esrc[j], s1 = esrc[j + 1];
        float x0 = als[s0 * H1 + h] + adh;
        float x1 = als[s1 * H1 + h] + adh;
        uint4 v0 = *reinterpret_cast<const uint4*>(&h1p[s0 * HC1 + ch0]);
        uint4 v1 = *reinterpret_cast<const uint4*>(&h1p[s1 * HC1 + ch0]);
        float w0 = wfun(x0), w1 = wfun(x1);
        den += w0 + w1;
        const unsigned u0[4] = {v0.x, v0.y, v0.z, v0.w};
        const unsigned u1[4] = {v1.x, v1.y, v1.z, v1.w};
#pragma unroll
        for (int q = 0; q < 4; q++) {
            float2 f0 = __half22float2(*reinterpret_cast<const __half2*>(&u0[q]));
            float2 f1 = __half22float2(*reinterpret_cast<const __half2*>(&u1[q]));
            acc[2 * q + 0] += w0 * f0.x + w1 * f1.x;
            acc[2 * q + 1] += w0 * f0.y + w1 * f1.y;
        }
    }
    if (j < j1) {
        int s0 = esrc[j];
        float x0 = als[s0 * H1 + h] + adh;
        uint4 v0 = *reinterpret_cast<const uint4*>(&h1p[s0 * HC1 + ch0]);
        float w0 = wfun(x0);
        den += w0;
        const unsigned u0[4] = {v0.x, v0.y, v0.z, v0.w};
#pragma unroll
        for (int q = 0; q < 4; q++) {
            float2 f0 = __half22float2(*reinterpret_cast<const __half2*>(&u0[q]));
            acc[2 * q + 0] += w0 * f0.x;
            acc[2 * q + 1] += w0 * f0.y;
        }
    }
    float inv = 1.f / den;               // self-loop guarantees den > 0
    float4 ba = *reinterpret_cast<const float4*>(&b1[ch0]);
    float4 bb = *reinterpret_cast<const float4*>(&b1[ch0 + 4]);
    float ob[8];
    ob[0] = acc[0] * inv + ba.x; ob[1] = acc[1] * inv + ba.y;
    ob[2] = acc[2] * inv + ba.z; ob[3] = acc[3] * inv + ba.w;
    ob[4] = acc[4] * inv + bb.x; ob[5] = acc[5] * inv + bb.y;
    ob[6] = acc[6] * inv + bb.z; ob[7] = acc[7] * inv + bb.w;
#pragma unroll
    for (int q = 0; q < 8; q++) ob[q] = ob[q] > 0.f ? ob[q] : expm1f(ob[q]);
    uint4 o;
    __half2 p0 = __floats2half2_rn(ob[0], ob[1]);
    __half2 p1 = __floats2half2_rn(ob[2], ob[3]);
    __half2 p2 = __floats2half2_rn(ob[4], ob[5]);
    __half2 p3 = __floats2half2_rn(ob[6], ob[7]);
    o.x = *reinterpret_cast<unsigned*>(&p0);
    o.y = *reinterpret_cast<unsigned*>(&p1);
    o.z = *reinterpret_cast<unsigned*>(&p2);
    o.w = *reinterpret_cast<unsigned*>(&p3);
    *reinterpret_cast<uint4*>(&g_out1h[d * HC1 + ch0]) = o;
}

// ---------------- GEMM2 + fused logits2 (8 rows x 4 cols per thread) --------
// 128 threads / 128-row blocks: ~7 blocks/SM resident, finer wave quantization
#define G2_ROWS 128
#define G2_PAD  132
__global__ __launch_bounds__(128) void gemm2_kernel(const float* __restrict__ W2,
                                                    const float* __restrict__ asrc,
                                                    const float* __restrict__ adst) {
    __shared__ float xst[32][G2_PAD];    // ~16.9 KB  [k][row]
    __shared__ float Wc[32][OUTC];       // 4 KB      [k][col] (current K-chunk)
    int tid = threadIdx.x;               // 128
    int row0 = blockIdx.x * G2_ROWS;
    int lane = tid & 31, w = tid >> 5;   // 4 warps
    int row_sub = lane >> 3;             // 0..3
    int cg = lane & 7;                   // 0..7
    int rbase = w * 32 + row_sub * 8;    // 8 consecutive rows per thread

    u64 acc2[4][4];                      // [row-pair][col]
#pragma unroll
    for (int m = 0; m < 4; m++)
#pragma unroll
        for (int c = 0; c < 4; c++) acc2[m][c] = 0ull;

#pragma unroll
    for (int kc = 0; kc < 4; kc++) {
        // load W chunk (32x32 floats = 256 float4 over 128 threads)
        {
            const float4* Wg = (const float4*)(W2 + kc * 32 * OUTC);
            ((float4*)Wc)[tid] = Wg[tid];
            ((float4*)Wc)[tid + 128] = Wg[tid + 128];
        }
        // load x chunk transposed: k8-major mapping (conflict-free STS)
#pragma unroll
        for (int i = 0; i < 4; i++) {
            int idx = tid + 128 * i;     // 0..511
            int k8 = idx >> 7;           // 0..3
            int row = idx & 127;
            int grow = row0 + row;
            uint4 v = make_uint4(0u, 0u, 0u, 0u);
            if (grow < NN) v = *(const uint4*)&g_out1h[grow * HC1 + kc * 32 + k8 * 8];
            const unsigned uu[4] = {v.x, v.y, v.z, v.w};
#pragma unroll
            for (int q = 0; q < 4; q++) {
                __half2 hh = *reinterpret_cast<const __half2*>(&uu[q]);
                float2 ff = __half22float2(hh);
                xst[k8 * 8 + q * 2 + 0][row] = ff.x;
                xst[k8 * 8 + q * 2 + 1][row] = ff.y;
            }
        }
        __syncthreads();

#pragma unroll 8
        for (int k = 0; k < 32; k++) {
            F4U2 xa, xb;
            xa.f4 = *(float4*)&xst[k][rbase];          // rows 0..3
            xb.f4 = *(float4*)&xst[k][rbase + 4];      // rows 4..7
            float4 wv = *(float4*)&Wc[k][cg * 4];      // 4 cols
            u64 wd0, wd1, wd2, wd3;
            PACK2(wd0, wv.x, wv.x); PACK2(wd1, wv.y, wv.y);
            PACK2(wd2, wv.z, wv.z); PACK2(wd3, wv.w, wv.w);
            u64 xp[4] = {xa.u[0], xa.u[1], xb.u[0], xb.u[1]};
#pragma unroll
            for (int m = 0; m < 4; m++) {
                FMA_X2(acc2[m][0], xp[m], wd0, acc2[m][0]);
                FMA_X2(acc2[m][1], xp[m], wd1, acc2[m][1]);
                FMA_X2(acc2[m][2], xp[m], wd2, acc2[m][2]);
                FMA_X2(acc2[m][3], xp[m], wd3, acc2[m][3]);
            }
        }
        __syncthreads();
    }

    float acc[8][4];                     // [row][col]
#pragma unroll
    for (int m = 0; m < 4; m++)
#pragma unroll
        for (int c = 0; c < 4; c++)
            UNPACK2(acc[2 * m][c], acc[2 * m + 1][c], acc2[m][c]);

    float4 av = *(const float4*)&asrc[cg * 4];
    float4 bv = *(const float4*)&adst[cg * 4];
#pragma unroll
    for (int r = 0; r < 8; r++) {
        int row = row0 + rbase + r;
        if (row < NN)
            *(float4*)&g_h2f[row * OUTC + cg * 4] = *(float4*)acc[r];
        float ps = acc[r][0] * av.x + acc[r][1] * av.y + acc[r][2] * av.z + acc[r][3] * av.w;
        float pd = acc[r][0] * bv.x + acc[r][1] * bv.y + acc[r][2] * bv.z + acc[r][3] * bv.w;
#pragma unroll
        for (int off = 4; off >= 1; off >>= 1) {
            ps += __shfl_down_sync(0xffffffffu, ps, off);
            pd += __shfl_down_sync(0xffffffffu, pd, off);
        }
        if (cg == 0 && row < NN) {
            g_al_src2[row] = ps * LOG2E;
            g_al_dst2[row] = pd * LOG2E;
        }
    }
}

// ---------------- fused agg2: QUARTER-warp per dst node (4 nodes/warp) ------
// lane = q*8 + sl; node q in 0..3; sl covers channels [sl*4, sl*4+4) as float4
__global__ void agg2_kernel(float* __restrict__ dout, const float* __restrict__ b2) {
    int gid = blockIdx.x * blockDim.x + threadIdx.x;
    int wid = gid >> 5;
    int lane = gid & 31;
    int q = lane >> 3;
    int sl = lane & 7;
    int d = wid * 4 + q;
    if (d >= NN) return;
    int ch0 = sl * 4;
    const float* __restrict__ als = g_al_src2;
    const int* __restrict__ esrc = g_esrc;
    const float* __restrict__ h2p = g_h2f;
    float ad2 = g_al_dst2[d];
    int j0 = g_off[d], j1 = g_off[d + 1];
    float4 acc = make_float4(0.f, 0.f, 0.f, 0.f);
    float den = 0.f;
    int j = j0;
    for (; j + 1 < j1; j += 2) {
        int s0 = esrc[j], s1 = esrc[j + 1];
        float x0 = als[s0] + ad2;
        float x1 = als[s1] + ad2;
        float4 v0 = *reinterpret_cast<const float4*>(&h2p[s0 * OUTC + ch0]);
        float4 v1 = *reinterpret_cast<const float4*>(&h2p[s1 * OUTC + ch0]);
        float w0 = wfun(x0), w1 = wfun(x1);
        den += w0 + w1;
        acc.x += w0 * v0.x + w1 * v1.x;
        acc.y += w0 * v0.y + w1 * v1.y;
        acc.z += w0 * v0.z + w1 * v1.z;
        acc.w += w0 * v0.w + w1 * v1.w;
    }
    if (j < j1) {
        int s0 = esrc[j];
        float w0 = wfun(als[s0] + ad2);
        float4 v0 = *reinterpret_cast<const float4*>(&h2p[s0 * OUTC + ch0]);
        den += w0;
        acc.x += w0 * v0.x; acc.y += w0 * v0.y;
        acc.z += w0 * v0.z; acc.w += w0 * v0.w;
    }
    float inv = 1.f / den;
    float4 bb = *reinterpret_cast<const float4*>(&b2[ch0]);
    float4 o;
    o.x = acc.x * inv + bb.x;
    o.y = acc.y * inv + bb.y;
    o.z = acc.z * inv + bb.z;
    o.w = acc.w * inv + bb.w;
    *reinterpret_cast<float4*>(&dout[d * OUTC + ch0]) = o;
}

// ---------------- launch ----------------
extern "C" void kernel_launch(void* const* d_in, const int* in_sizes, int n_in,
                              void* d_out, int out_size) {
    const float* x        = (const float*)d_in[0];
    const int*   ei       = (const int*)d_in[1];
    const float* W1       = (const float*)d_in[2];
    const float* att_src1 = (const float*)d_in[3];
    const float* att_dst1 = (const float*)d_in[4];
    const float* b1       = (const float*)d_in[5];
    const float* W2       = (const float*)d_in[6];
    const float* att_src2 = (const float*)d_in[7];
    const float* att_dst2 = (const float*)d_in[8];
    const float* b2       = (const float*)d_in[9];
    float* dout = (float*)d_out;

    const int T = 256;
    const long NW1 = (NN + 1) / 2;              // agg1: 2 nodes per warp
    const int AGG1_BLOCKS = (int)((NW1 * 32 + T - 1) / T);
    const long NW2 = (NN + 3) / 4;              // agg2: 4 nodes per warp
    const int AGG2_BLOCKS = (int)((NW2 * 32 + T - 1) / T);

    // host-side objects only (no device allocation); leaked intentionally —
    // kernel_launch runs O(1) times
    cudaStream_t s2;
    cudaStreamCreate(&s2);
    cudaEvent_t eFork, eH;
    cudaEventCreateWithFlags(&eFork, cudaEventDisableTiming);
    cudaEventCreateWithFlags(&eH,    cudaEventDisableTiming);

    // fork: CSR build (self-initializing) runs concurrently with gemm1
    cudaEventRecord(eFork, 0);
    cudaStreamWaitEvent(s2, eFork, 0);
    histscan_kernel<<<NB_SCAN, 1024, 0, s2>>>(ei);
    cudaEventRecord(eH, s2);

    gemm1_kernel<<<(NN + G1_ROWS - 1) / G1_ROWS, 256>>>(x, W1, att_src1, att_dst1);

    cudaStreamWaitEvent(0, eH, 0);
    agg1_kernel<<<AGG1_BLOCKS, T>>>(b1);
    gemm2_kernel<<<(NN + G2_ROWS - 1) / G2_ROWS, 128>>>(W2, att_src2, att_dst2);
    agg2_kernel<<<AGG2_BLOCKS, T>>>(dout, b2);
}